// round 5
// baseline (speedup 1.0000x reference)
#include <cuda_runtime.h>
#include <cstdint>
#include <cstddef>

// Problem constants
#define DMODEL 1024
#define HEADS  16
#define DKEY   64
#define BATCH  4
#define SEQ    2048
#define MROWS  (BATCH * SEQ)   // 8192

// -------- scratch (static device arrays; no allocation allowed) --------
__device__ float g_qp[(size_t)BATCH * HEADS * SEQ * DKEY];  // [B,H,S,K]
__device__ float g_kp[(size_t)BATCH * HEADS * SEQ * DKEY];
__device__ float g_vp[(size_t)BATCH * HEADS * SEQ * DKEY];
__device__ float g_ao[(size_t)MROWS * DMODEL];              // [B*S, H*K]

__device__ __forceinline__ float fast_exp2(float x) {
    float y;
    asm("ex2.approx.f32 %0, %1;" : "=f"(y) : "f"(x));
    return y;
}

// ======================= GEMM: C = A (MxKd) * B^T (NxKd) =======================
// A row-major [M, 1024], B row-major [N=1024, 1024] (torch Linear weight layout).
// mode 0: C[m*1024 + n] plain row-major.
// mode 1: scatter to [B,H,S,K]: m=(b,s), n=(h,k).
static constexpr int GBM = 128, GBN = 128, GBK = 16, GP = 132;

__global__ void __launch_bounds__(256, 2) gemm_abt_kernel(
    const float* __restrict__ A, const float* __restrict__ B,
    float* __restrict__ C, int mode)
{
    __shared__ float As[GBK * GP];
    __shared__ float Bs[GBK * GP];

    const int Kd = DMODEL;
    const int bm = blockIdx.y * GBM;
    const int bn = blockIdx.x * GBN;
    const int tid = threadIdx.x;
    const int tm = tid >> 4;     // 0..15
    const int tn = tid & 15;     // 0..15

    float acc[8][8];
#pragma unroll
    for (int i = 0; i < 8; i++)
#pragma unroll
        for (int j = 0; j < 8; j++) acc[i][j] = 0.0f;

    for (int k0 = 0; k0 < Kd; k0 += GBK) {
        // Load A tile 128x16 and B tile 128x16, transposed into [k][m] layout.
#pragma unroll
        for (int it = 0; it < 2; it++) {
            int idx = tid + it * 256;         // 0..511
            int row = idx >> 2;               // 0..127
            int kq  = idx & 3;                // 0..3  (k = kq*4 + j)
            float4 va = *(const float4*)(A + (size_t)(bm + row) * Kd + k0 + kq * 4);
            As[(kq * 4 + 0) * GP + row] = va.x;
            As[(kq * 4 + 1) * GP + row] = va.y;
            As[(kq * 4 + 2) * GP + row] = va.z;
            As[(kq * 4 + 3) * GP + row] = va.w;
            float4 vb = *(const float4*)(B + (size_t)(bn + row) * Kd + k0 + kq * 4);
            Bs[(kq * 4 + 0) * GP + row] = vb.x;
            Bs[(kq * 4 + 1) * GP + row] = vb.y;
            Bs[(kq * 4 + 2) * GP + row] = vb.z;
            Bs[(kq * 4 + 3) * GP + row] = vb.w;
        }
        __syncthreads();

#pragma unroll
        for (int k = 0; k < GBK; k++) {
            float a[8], b[8];
            *(float4*)&a[0] = *(const float4*)&As[k * GP + tm * 8];
            *(float4*)&a[4] = *(const float4*)&As[k * GP + tm * 8 + 4];
            *(float4*)&b[0] = *(const float4*)&Bs[k * GP + tn * 8];
            *(float4*)&b[4] = *(const float4*)&Bs[k * GP + tn * 8 + 4];
#pragma unroll
            for (int i = 0; i < 8; i++)
#pragma unroll
                for (int j = 0; j < 8; j++)
                    acc[i][j] = fmaf(a[i], b[j], acc[i][j]);
        }
        __syncthreads();
    }

    // Store
#pragma unroll
    for (int i = 0; i < 8; i++) {
        int m = bm + tm * 8 + i;
        int n0 = bn + tn * 8;
        float4 v0 = make_float4(acc[i][0], acc[i][1], acc[i][2], acc[i][3]);
        float4 v1 = make_float4(acc[i][4], acc[i][5], acc[i][6], acc[i][7]);
        if (mode == 0) {
            float4* p = (float4*)(C + (size_t)m * DMODEL + n0);
            p[0] = v0;
            p[1] = v1;
        } else {
            int b = m >> 11;          // m / SEQ
            int s = m & (SEQ - 1);
            int h = n0 >> 6;          // n0 / DKEY  (8-col group stays within one head)
            int kk = n0 & (DKEY - 1);
            float* base = C + ((((size_t)b * HEADS + h) * SEQ) + s) * DKEY + kk;
            ((float4*)base)[0] = v0;
            ((float4*)base)[1] = v1;
        }
    }
}

// ======================= Flash attention (fp32) =======================
// One CTA per (b, h, 64-query tile). 256 threads; each thread owns a 4x4
// microtile of the 64x64 score block and a 4x4 microtile of the 64x64 O block.
static constexpr int FT = 64, FP = 68;
static constexpr float SM_SCALE = 0.18033688011117310f; // (1/8) * log2(e)

__global__ void __launch_bounds__(256) flash_kernel()
{
    extern __shared__ float sm[];
    float* Qs = sm;                // [q][d]  pitch FP
    float* Ks = sm + FT * FP;      // [d][kv] pitch FP (transposed)
    float* Vs = sm + 2 * FT * FP;  // [kv][d] pitch FP
    float* Ps = sm + 3 * FT * FP;  // [q][kv] pitch FP

    const int b  = blockIdx.z;
    const int h  = blockIdx.y;
    const int qt = blockIdx.x;
    const int tid = threadIdx.x;
    const int tr = tid >> 4;   // 0..15: q rows tr*4..tr*4+3
    const int tc = tid & 15;   // 0..15: cols tc*4..tc*4+3

    const float* Qg = g_qp + (((size_t)b * HEADS + h) * SEQ + qt * FT) * DKEY;
    const float* Kg = g_kp + ((size_t)b * HEADS + h) * SEQ * DKEY;
    const float* Vg = g_vp + ((size_t)b * HEADS + h) * SEQ * DKEY;

    // Load Q tile [64 q][64 d]
#pragma unroll
    for (int it = 0; it < 4; it++) {
        int idx = tid + it * 256;       // 0..1023
        int row = idx >> 4;             // 0..63
        int dq  = idx & 15;             // 0..15
        *(float4*)&Qs[row * FP + dq * 4] = *(const float4*)(Qg + row * DKEY + dq * 4);
    }

    float o[4][4];
    float mrun[4], lrun[4];
#pragma unroll
    for (int i = 0; i < 4; i++) {
        mrun[i] = -3.0e38f;
        lrun[i] = 0.0f;
#pragma unroll
        for (int j = 0; j < 4; j++) o[i][j] = 0.0f;
    }

    for (int t = 0; t < SEQ / FT; t++) {
        // Load K tile transposed into Ks[d][kv]
        const float* Kt = Kg + (size_t)t * FT * DKEY;
#pragma unroll
        for (int it = 0; it < 4; it++) {
            int idx = tid + it * 256;
            int row = idx >> 4;         // kv
            int dq  = idx & 15;
            float4 v = *(const float4*)(Kt + row * DKEY + dq * 4);
            Ks[(dq * 4 + 0) * FP + row] = v.x;
            Ks[(dq * 4 + 1) * FP + row] = v.y;
            Ks[(dq * 4 + 2) * FP + row] = v.z;
            Ks[(dq * 4 + 3) * FP + row] = v.w;
        }
        __syncthreads();   // K ready (also guarantees prior P/V reads completed)

        // S = Q * K^T  (4x4 per thread)
        float s[4][4];
#pragma unroll
        for (int i = 0; i < 4; i++)
#pragma unroll
            for (int j = 0; j < 4; j++) s[i][j] = 0.0f;

#pragma unroll 8
        for (int d = 0; d < FT; d++) {
            float qv[4];
#pragma unroll
            for (int i = 0; i < 4; i++) qv[i] = Qs[(tr * 4 + i) * FP + d];
            float4 kf = *(const float4*)&Ks[d * FP + tc * 4];
            float kb[4] = {kf.x, kf.y, kf.z, kf.w};
#pragma unroll
            for (int i = 0; i < 4; i++)
#pragma unroll
                for (int j = 0; j < 4; j++)
                    s[i][j] = fmaf(qv[i], kb[j], s[i][j]);
        }

        // Online softmax + write P
#pragma unroll
        for (int i = 0; i < 4; i++) {
#pragma unroll
            for (int j = 0; j < 4; j++) s[i][j] *= SM_SCALE;
            float mx = fmaxf(fmaxf(s[i][0], s[i][1]), fmaxf(s[i][2], s[i][3]));
#pragma unroll
            for (int off = 8; off > 0; off >>= 1)
                mx = fmaxf(mx, __shfl_xor_sync(0xffffffffu, mx, off));
            float mn = fmaxf(mrun[i], mx);
            float corr = fast_exp2(mrun[i] - mn);
            mrun[i] = mn;
            float rs = 0.0f;
#pragma unroll
            for (int j = 0; j < 4; j++) {
                s[i][j] = fast_exp2(s[i][j] - mn);
                rs += s[i][j];
            }
#pragma unroll
            for (int off = 8; off > 0; off >>= 1)
                rs += __shfl_xor_sync(0xffffffffu, rs, off);
            lrun[i] = lrun[i] * corr + rs;
#pragma unroll
            for (int j = 0; j < 4; j++) o[i][j] *= corr;
            *(float4*)&Ps[(tr * 4 + i) * FP + tc * 4] =
                make_float4(s[i][0], s[i][1], s[i][2], s[i][3]);
        }

        // Load V tile [kv][d]
        const float* Vt = Vg + (size_t)t * FT * DKEY;
#pragma unroll
        for (int it = 0; it < 4; it++) {
            int idx = tid + it * 256;
            int row = idx >> 4;
            int dq  = idx & 15;
            *(float4*)&Vs[row * FP + dq * 4] = *(const float4*)(Vt + row * DKEY + dq * 4);
        }
        __syncthreads();   // P and V ready

        // O += P * V
#pragma unroll 8
        for (int kv = 0; kv < FT; kv++) {
            float pr[4];
#pragma unroll
            for (int i = 0; i < 4; i++) pr[i] = Ps[(tr * 4 + i) * FP + kv];
            float4 vf = *(const float4*)&Vs[kv * FP + tc * 4];
            float vb[4] = {vf.x, vf.y, vf.z, vf.w};
#pragma unroll
            for (int i = 0; i < 4; i++)
#pragma unroll
                for (int j = 0; j < 4; j++)
                    o[i][j] = fmaf(pr[i], vb[j], o[i][j]);
        }
    }

    // Epilogue: normalize and write concat-head layout [B*S, H*K]
#pragma unroll
    for (int i = 0; i < 4; i++) {
        float inv = 1.0f / lrun[i];
        int m = b * SEQ + qt * FT + tr * 4 + i;
        float4 ov = make_float4(o[i][0] * inv, o[i][1] * inv,
                                o[i][2] * inv, o[i][3] * inv);
        *(float4*)(g_ao + (size_t)m * DMODEL + h * DKEY + tc * 4) = ov;
    }
}

// ======================= launch =======================
extern "C" void kernel_launch(void* const* d_in, const int* in_sizes, int n_in,
                              void* d_out, int out_size)
{
    const float* q_in  = (const float*)d_in[0];
    const float* k_in  = (const float*)d_in[1];
    const float* v_in  = (const float*)d_in[2];
    const float* Wq    = (const float*)d_in[3];
    const float* Wk    = (const float*)d_in[4];
    const float* Wv    = (const float*)d_in[5];
    const float* Wo    = (const float*)d_in[6];
    float* out = (float*)d_out;

    float *qp, *kp, *vp, *ao;
    cudaGetSymbolAddress((void**)&qp, g_qp);
    cudaGetSymbolAddress((void**)&kp, g_kp);
    cudaGetSymbolAddress((void**)&vp, g_vp);
    cudaGetSymbolAddress((void**)&ao, g_ao);

    dim3 ggrid(DMODEL / GBN, MROWS / GBM);   // (8, 64)

    gemm_abt_kernel<<<ggrid, 256>>>(q_in, Wq, qp, 1);
    gemm_abt_kernel<<<ggrid, 256>>>(k_in, Wk, kp, 1);
    gemm_abt_kernel<<<ggrid, 256>>>(v_in, Wv, vp, 1);

    size_t shbytes = (size_t)4 * FT * FP * sizeof(float);  // 69632 bytes
    cudaFuncSetAttribute(flash_kernel,
                         cudaFuncAttributeMaxDynamicSharedMemorySize,
                         (int)shbytes);
    flash_kernel<<<dim3(SEQ / FT, HEADS, BATCH), 256, shbytes>>>();

    gemm_abt_kernel<<<ggrid, 256>>>(ao, Wo, out, 0);
}

// round 7
// speedup vs baseline: 1.2945x; 1.2945x over previous
#include <cuda_runtime.h>
#include <cstdint>
#include <cstddef>

// Problem constants
#define DMODEL 1024
#define HEADS  16
#define DKEY   64
#define BATCH  4
#define SEQ    2048
#define MROWS  (BATCH * SEQ)   // 8192

// -------- scratch (static device arrays; no allocation allowed) --------
__device__ float g_qp[(size_t)BATCH * HEADS * SEQ * DKEY];  // [B,H,S,K]
__device__ float g_kp[(size_t)BATCH * HEADS * SEQ * DKEY];
__device__ float g_vp[(size_t)BATCH * HEADS * SEQ * DKEY];
__device__ float g_ao[(size_t)MROWS * DMODEL];              // [B*S, H*K]

__device__ __forceinline__ float fast_exp2(float x) {
    float y;
    asm("ex2.approx.f32 %0, %1;" : "=f"(y) : "f"(x));
    return y;
}
__device__ __forceinline__ float to_tf32(float x) {
    float y;
    asm("cvt.rna.tf32.f32 %0, %1;" : "=f"(y) : "f"(x));
    return y;
}

// m16n8k8 tf32 mma: D = A(16x8,row) * B(8x8,col) + D
__device__ __forceinline__ void mma_tf32(float* c, const uint32_t* a, const uint32_t* b) {
    asm volatile(
        "mma.sync.aligned.m16n8k8.row.col.f32.tf32.tf32.f32 "
        "{%0,%1,%2,%3}, {%4,%5,%6,%7}, {%8,%9}, {%0,%1,%2,%3};"
        : "+f"(c[0]), "+f"(c[1]), "+f"(c[2]), "+f"(c[3])
        : "r"(a[0]), "r"(a[1]), "r"(a[2]), "r"(a[3]), "r"(b[0]), "r"(b[1]));
}

// ============ tf32 tensor-core GEMM: C = A (M x 1024) * B^T (N x 1024) ========
// A row-major [M,1024]; B row-major [N,1024] (torch Linear weight layout).
// Block 128x128, BK=32. 8 warps in 2(M) x 4(N) grid; warp tile 64x32.
// mode 0: C row-major [M,1024]. mode 1: scatter to [B,H,S,K].
static constexpr int BM = 128, BN = 128, BK = 32;
static constexpr int TPITCH = 132;  // floats per k-row in smem (conflict-free)

__global__ void __launch_bounds__(256) gemm_mma_kernel(
    const float* __restrict__ A, const float* __restrict__ B,
    float* __restrict__ C, int mode)
{
    __shared__ float As[BK * TPITCH];   // [k][m]
    __shared__ float Bs[BK * TPITCH];   // [k][n]

    const int tid  = threadIdx.x;
    const int wid  = tid >> 5;
    const int lane = tid & 31;
    const int gid  = lane >> 2;   // 0..7
    const int tig  = lane & 3;    // 0..3
    const int wm = (wid >> 2) * 64;   // warp M offset in block
    const int wn = (wid & 3) * 32;    // warp N offset in block
    const int bm = blockIdx.y * BM;
    const int bn = blockIdx.x * BN;

    float acc[4][4][4];
#pragma unroll
    for (int mt = 0; mt < 4; mt++)
#pragma unroll
        for (int nt = 0; nt < 4; nt++)
#pragma unroll
            for (int r = 0; r < 4; r++) acc[mt][nt][r] = 0.0f;

    for (int k0 = 0; k0 < DMODEL; k0 += BK) {
        // Load A/B tiles (128 rows x 32 k), transpose into [k][row], cvt to tf32.
#pragma unroll
        for (int it = 0; it < 4; it++) {
            int idx = tid + it * 256;        // 0..1023
            int row = idx >> 3;              // 0..127
            int kq  = idx & 7;               // quad: k = kq*4..kq*4+3
            float4 va = *(const float4*)(A + (size_t)(bm + row) * DMODEL + k0 + kq * 4);
            As[(kq * 4 + 0) * TPITCH + row] = to_tf32(va.x);
            As[(kq * 4 + 1) * TPITCH + row] = to_tf32(va.y);
            As[(kq * 4 + 2) * TPITCH + row] = to_tf32(va.z);
            As[(kq * 4 + 3) * TPITCH + row] = to_tf32(va.w);
            float4 vb = *(const float4*)(B + (size_t)(bn + row) * DMODEL + k0 + kq * 4);
            Bs[(kq * 4 + 0) * TPITCH + row] = to_tf32(vb.x);
            Bs[(kq * 4 + 1) * TPITCH + row] = to_tf32(vb.y);
            Bs[(kq * 4 + 2) * TPITCH + row] = to_tf32(vb.z);
            Bs[(kq * 4 + 3) * TPITCH + row] = to_tf32(vb.w);
        }
        __syncthreads();

#pragma unroll
        for (int ks = 0; ks < 4; ks++) {
            const int kk = ks * 8;
            uint32_t afrag[4][4], bfrag[4][2];
#pragma unroll
            for (int mt = 0; mt < 4; mt++) {
                const int m0 = wm + mt * 16;
                afrag[mt][0] = __float_as_uint(As[(kk + tig) * TPITCH + m0 + gid]);
                afrag[mt][1] = __float_as_uint(As[(kk + tig) * TPITCH + m0 + gid + 8]);
                afrag[mt][2] = __float_as_uint(As[(kk + tig + 4) * TPITCH + m0 + gid]);
                afrag[mt][3] = __float_as_uint(As[(kk + tig + 4) * TPITCH + m0 + gid + 8]);
            }
#pragma unroll
            for (int nt = 0; nt < 4; nt++) {
                const int n0 = wn + nt * 8;
                bfrag[nt][0] = __float_as_uint(Bs[(kk + tig) * TPITCH + n0 + gid]);
                bfrag[nt][1] = __float_as_uint(Bs[(kk + tig + 4) * TPITCH + n0 + gid]);
            }
#pragma unroll
            for (int mt = 0; mt < 4; mt++)
#pragma unroll
                for (int nt = 0; nt < 4; nt++)
                    mma_tf32(acc[mt][nt], afrag[mt], bfrag[nt]);
        }
        __syncthreads();
    }

    // Epilogue: c0,c1 -> (row, col+{0,1}); c2,c3 -> (row+8, col+{0,1})
#pragma unroll
    for (int mt = 0; mt < 4; mt++) {
        const int r0 = bm + wm + mt * 16 + gid;
#pragma unroll
        for (int half = 0; half < 2; half++) {
            const int r = r0 + half * 8;
            const int b = r >> 11;            // r / SEQ
            const int s = r & (SEQ - 1);
#pragma unroll
            for (int nt = 0; nt < 4; nt++) {
                const int col = bn + wn + nt * 8 + tig * 2;
                float2 v = make_float2(acc[mt][nt][half * 2],
                                       acc[mt][nt][half * 2 + 1]);
                if (mode == 0) {
                    *(float2*)(C + (size_t)r * DMODEL + col) = v;
                } else {
                    const int h  = col >> 6;
                    const int kk = col & (DKEY - 1);
                    *(float2*)(C + ((((size_t)b * HEADS + h) * SEQ) + s) * DKEY + kk) = v;
                }
            }
        }
    }
}

// ======================= Flash attention (fp32, unchanged) =======================
static constexpr int FT = 64, FP = 68;
static constexpr float SM_SCALE = 0.18033688011117310f; // (1/8) * log2(e)

__global__ void __launch_bounds__(256) flash_kernel()
{
    extern __shared__ float sm[];
    float* Qs = sm;                // [q][d]  pitch FP
    float* Ks = sm + FT * FP;      // [d][kv] pitch FP (transposed)
    float* Vs = sm + 2 * FT * FP;  // [kv][d] pitch FP
    float* Ps = sm + 3 * FT * FP;  // [q][kv] pitch FP

    const int b  = blockIdx.z;
    const int h  = blockIdx.y;
    const int qt = blockIdx.x;
    const int tid = threadIdx.x;
    const int tr = tid >> 4;   // 0..15: q rows tr*4..tr*4+3
    const int tc = tid & 15;   // 0..15: cols tc*4..tc*4+3

    const float* Qg = g_qp + (((size_t)b * HEADS + h) * SEQ + qt * FT) * DKEY;
    const float* Kg = g_kp + ((size_t)b * HEADS + h) * SEQ * DKEY;
    const float* Vg = g_vp + ((size_t)b * HEADS + h) * SEQ * DKEY;

    // Load Q tile [64 q][64 d]
#pragma unroll
    for (int it = 0; it < 4; it++) {
        int idx = tid + it * 256;       // 0..1023
        int row = idx >> 4;             // 0..63
        int dq  = idx & 15;             // 0..15
        *(float4*)&Qs[row * FP + dq * 4] = *(const float4*)(Qg + row * DKEY + dq * 4);
    }

    float o[4][4];
    float mrun[4], lrun[4];
#pragma unroll
    for (int i = 0; i < 4; i++) {
        mrun[i] = -3.0e38f;
        lrun[i] = 0.0f;
#pragma unroll
        for (int j = 0; j < 4; j++) o[i][j] = 0.0f;
    }

    for (int t = 0; t < SEQ / FT; t++) {
        // Load K tile transposed into Ks[d][kv]
        const float* Kt = Kg + (size_t)t * FT * DKEY;
#pragma unroll
        for (int it = 0; it < 4; it++) {
            int idx = tid + it * 256;
            int row = idx >> 4;         // kv
            int dq  = idx & 15;
            float4 v = *(const float4*)(Kt + row * DKEY + dq * 4);
            Ks[(dq * 4 + 0) * FP + row] = v.x;
            Ks[(dq * 4 + 1) * FP + row] = v.y;
            Ks[(dq * 4 + 2) * FP + row] = v.z;
            Ks[(dq * 4 + 3) * FP + row] = v.w;
        }
        __syncthreads();   // K ready (also guarantees prior P/V reads completed)

        // S = Q * K^T  (4x4 per thread)
        float s[4][4];
#pragma unroll
        for (int i = 0; i < 4; i++)
#pragma unroll
            for (int j = 0; j < 4; j++) s[i][j] = 0.0f;

#pragma unroll 8
        for (int d = 0; d < FT; d++) {
            float qv[4];
#pragma unroll
            for (int i = 0; i < 4; i++) qv[i] = Qs[(tr * 4 + i) * FP + d];
            float4 kf = *(const float4*)&Ks[d * FP + tc * 4];
            float kb[4] = {kf.x, kf.y, kf.z, kf.w};
#pragma unroll
            for (int i = 0; i < 4; i++)
#pragma unroll
                for (int j = 0; j < 4; j++)
                    s[i][j] = fmaf(qv[i], kb[j], s[i][j]);
        }

        // Online softmax + write P
#pragma unroll
        for (int i = 0; i < 4; i++) {
#pragma unroll
            for (int j = 0; j < 4; j++) s[i][j] *= SM_SCALE;
            float mx = fmaxf(fmaxf(s[i][0], s[i][1]), fmaxf(s[i][2], s[i][3]));
#pragma unroll
            for (int off = 8; off > 0; off >>= 1)
                mx = fmaxf(mx, __shfl_xor_sync(0xffffffffu, mx, off));
            float mn = fmaxf(mrun[i], mx);
            float corr = fast_exp2(mrun[i] - mn);
            mrun[i] = mn;
            float rs = 0.0f;
#pragma unroll
            for (int j = 0; j < 4; j++) {
                s[i][j] = fast_exp2(s[i][j] - mn);
                rs += s[i][j];
            }
#pragma unroll
            for (int off = 8; off > 0; off >>= 1)
                rs += __shfl_xor_sync(0xffffffffu, rs, off);
            lrun[i] = lrun[i] * corr + rs;
#pragma unroll
            for (int j = 0; j < 4; j++) o[i][j] *= corr;
            *(float4*)&Ps[(tr * 4 + i) * FP + tc * 4] =
                make_float4(s[i][0], s[i][1], s[i][2], s[i][3]);
        }

        // Load V tile [kv][d]
        const float* Vt = Vg + (size_t)t * FT * DKEY;
#pragma unroll
        for (int it = 0; it < 4; it++) {
            int idx = tid + it * 256;
            int row = idx >> 4;
            int dq  = idx & 15;
            *(float4*)&Vs[row * FP + dq * 4] = *(const float4*)(Vt + row * DKEY + dq * 4);
        }
        __syncthreads();   // P and V ready

        // O += P * V
#pragma unroll 8
        for (int kv = 0; kv < FT; kv++) {
            float pr[4];
#pragma unroll
            for (int i = 0; i < 4; i++) pr[i] = Ps[(tr * 4 + i) * FP + kv];
            float4 vf = *(const float4*)&Vs[kv * FP + tc * 4];
            float vb[4] = {vf.x, vf.y, vf.z, vf.w};
#pragma unroll
            for (int i = 0; i < 4; i++)
#pragma unroll
                for (int j = 0; j < 4; j++)
                    o[i][j] = fmaf(pr[i], vb[j], o[i][j]);
        }
    }

    // Epilogue: normalize and write concat-head layout [B*S, H*K]
#pragma unroll
    for (int i = 0; i < 4; i++) {
        float inv = 1.0f / lrun[i];
        int m = b * SEQ + qt * FT + tr * 4 + i;
        float4 ov = make_float4(o[i][0] * inv, o[i][1] * inv,
                                o[i][2] * inv, o[i][3] * inv);
        *(float4*)(g_ao + (size_t)m * DMODEL + h * DKEY + tc * 4) = ov;
    }
}

// ======================= launch =======================
extern "C" void kernel_launch(void* const* d_in, const int* in_sizes, int n_in,
                              void* d_out, int out_size)
{
    const float* q_in  = (const float*)d_in[0];
    const float* k_in  = (const float*)d_in[1];
    const float* v_in  = (const float*)d_in[2];
    const float* Wq    = (const float*)d_in[3];
    const float* Wk    = (const float*)d_in[4];
    const float* Wv    = (const float*)d_in[5];
    const float* Wo    = (const float*)d_in[6];
    float* out = (float*)d_out;

    float *qp, *kp, *vp, *ao;
    cudaGetSymbolAddress((void**)&qp, g_qp);
    cudaGetSymbolAddress((void**)&kp, g_kp);
    cudaGetSymbolAddress((void**)&vp, g_vp);
    cudaGetSymbolAddress((void**)&ao, g_ao);

    dim3 ggrid(DMODEL / BN, MROWS / BM);   // (8, 64)

    gemm_mma_kernel<<<ggrid, 256>>>(q_in, Wq, qp, 1);
    gemm_mma_kernel<<<ggrid, 256>>>(k_in, Wk, kp, 1);
    gemm_mma_kernel<<<ggrid, 256>>>(v_in, Wv, vp, 1);

    size_t shbytes = (size_t)4 * FT * FP * sizeof(float);  // 69632 bytes
    cudaFuncSetAttribute(flash_kernel,
                         cudaFuncAttributeMaxDynamicSharedMemorySize,
                         (int)shbytes);
    flash_kernel<<<dim3(SEQ / FT, HEADS, BATCH), 256, shbytes>>>();

    gemm_mma_kernel<<<ggrid, 256>>>(ao, Wo, out, 0);
}

// round 9
// speedup vs baseline: 2.3159x; 1.7890x over previous
#include <cuda_runtime.h>
#include <cstdint>
#include <cstddef>

// Problem constants
#define DMODEL 1024
#define HEADS  16
#define DKEY   64
#define BATCH  4
#define SEQ    2048
#define MROWS  (BATCH * SEQ)   // 8192

// -------- scratch (static device arrays; no allocation allowed) --------
__device__ float g_qp[(size_t)BATCH * HEADS * SEQ * DKEY];  // [B,H,S,K]
__device__ float g_kp[(size_t)BATCH * HEADS * SEQ * DKEY];
__device__ float g_vp[(size_t)BATCH * HEADS * SEQ * DKEY];
__device__ float g_ao[(size_t)MROWS * DMODEL];              // [B*S, H*K]

__device__ __forceinline__ float fast_exp2(float x) {
    float y;
    asm("ex2.approx.f32 %0, %1;" : "=f"(y) : "f"(x));
    return y;
}
__device__ __forceinline__ float to_tf32(float x) {
    float y;
    asm("cvt.rna.tf32.f32 %0, %1;" : "=f"(y) : "f"(x));
    return y;
}

// m16n8k8 tf32 mma: D = A(16x8,row) * B(8x8,col) + D
__device__ __forceinline__ void mma_tf32(float* c, const uint32_t* a, const uint32_t* b) {
    asm volatile(
        "mma.sync.aligned.m16n8k8.row.col.f32.tf32.tf32.f32 "
        "{%0,%1,%2,%3}, {%4,%5,%6,%7}, {%8,%9}, {%0,%1,%2,%3};"
        : "+f"(c[0]), "+f"(c[1]), "+f"(c[2]), "+f"(c[3])
        : "r"(a[0]), "r"(a[1]), "r"(a[2]), "r"(a[3]), "r"(b[0]), "r"(b[1]));
}

// ============ tf32 tensor-core GEMM: C = A (M x 1024) * B^T (N x 1024) ========
static constexpr int BM = 128, BN = 128, BK = 32;
static constexpr int TPITCH = 132;  // floats per k-row in smem (conflict-free)

__global__ void __launch_bounds__(256) gemm_mma_kernel(
    const float* __restrict__ A, const float* __restrict__ B,
    float* __restrict__ C, int mode)
{
    __shared__ float As[BK * TPITCH];   // [k][m]
    __shared__ float Bs[BK * TPITCH];   // [k][n]

    const int tid  = threadIdx.x;
    const int wid  = tid >> 5;
    const int lane = tid & 31;
    const int gid  = lane >> 2;   // 0..7
    const int tig  = lane & 3;    // 0..3
    const int wm = (wid >> 2) * 64;   // warp M offset in block
    const int wn = (wid & 3) * 32;    // warp N offset in block
    const int bm = blockIdx.y * BM;
    const int bn = blockIdx.x * BN;

    float acc[4][4][4];
#pragma unroll
    for (int mt = 0; mt < 4; mt++)
#pragma unroll
        for (int nt = 0; nt < 4; nt++)
#pragma unroll
            for (int r = 0; r < 4; r++) acc[mt][nt][r] = 0.0f;

    for (int k0 = 0; k0 < DMODEL; k0 += BK) {
#pragma unroll
        for (int it = 0; it < 4; it++) {
            int idx = tid + it * 256;        // 0..1023
            int row = idx >> 3;              // 0..127
            int kq  = idx & 7;               // quad: k = kq*4..kq*4+3
            float4 va = *(const float4*)(A + (size_t)(bm + row) * DMODEL + k0 + kq * 4);
            As[(kq * 4 + 0) * TPITCH + row] = to_tf32(va.x);
            As[(kq * 4 + 1) * TPITCH + row] = to_tf32(va.y);
            As[(kq * 4 + 2) * TPITCH + row] = to_tf32(va.z);
            As[(kq * 4 + 3) * TPITCH + row] = to_tf32(va.w);
            float4 vb = *(const float4*)(B + (size_t)(bn + row) * DMODEL + k0 + kq * 4);
            Bs[(kq * 4 + 0) * TPITCH + row] = to_tf32(vb.x);
            Bs[(kq * 4 + 1) * TPITCH + row] = to_tf32(vb.y);
            Bs[(kq * 4 + 2) * TPITCH + row] = to_tf32(vb.z);
            Bs[(kq * 4 + 3) * TPITCH + row] = to_tf32(vb.w);
        }
        __syncthreads();

#pragma unroll
        for (int ks = 0; ks < 4; ks++) {
            const int kk = ks * 8;
            uint32_t afrag[4][4], bfrag[4][2];
#pragma unroll
            for (int mt = 0; mt < 4; mt++) {
                const int m0 = wm + mt * 16;
                afrag[mt][0] = __float_as_uint(As[(kk + tig) * TPITCH + m0 + gid]);
                afrag[mt][1] = __float_as_uint(As[(kk + tig) * TPITCH + m0 + gid + 8]);
                afrag[mt][2] = __float_as_uint(As[(kk + tig + 4) * TPITCH + m0 + gid]);
                afrag[mt][3] = __float_as_uint(As[(kk + tig + 4) * TPITCH + m0 + gid + 8]);
            }
#pragma unroll
            for (int nt = 0; nt < 4; nt++) {
                const int n0 = wn + nt * 8;
                bfrag[nt][0] = __float_as_uint(Bs[(kk + tig) * TPITCH + n0 + gid]);
                bfrag[nt][1] = __float_as_uint(Bs[(kk + tig + 4) * TPITCH + n0 + gid]);
            }
#pragma unroll
            for (int mt = 0; mt < 4; mt++)
#pragma unroll
                for (int nt = 0; nt < 4; nt++)
                    mma_tf32(acc[mt][nt], afrag[mt], bfrag[nt]);
        }
        __syncthreads();
    }

#pragma unroll
    for (int mt = 0; mt < 4; mt++) {
        const int r0 = bm + wm + mt * 16 + gid;
#pragma unroll
        for (int half = 0; half < 2; half++) {
            const int r = r0 + half * 8;
            const int b = r >> 11;            // r / SEQ
            const int s = r & (SEQ - 1);
#pragma unroll
            for (int nt = 0; nt < 4; nt++) {
                const int col = bn + wn + nt * 8 + tig * 2;
                float2 v = make_float2(acc[mt][nt][half * 2],
                                       acc[mt][nt][half * 2 + 1]);
                if (mode == 0) {
                    *(float2*)(C + (size_t)r * DMODEL + col) = v;
                } else {
                    const int h  = col >> 6;
                    const int kk = col & (DKEY - 1);
                    *(float2*)(C + ((((size_t)b * HEADS + h) * SEQ) + s) * DKEY + kk) = v;
                }
            }
        }
    }
}

// ======================= Flash attention (tf32 mma.sync) =======================
// CTA: 128 queries x full sequence, KV tiles of 64. 8 warps; warp w owns q rows
// [w*16, w*16+16). All matmuls on tensor cores (m16n8k8 tf32).
static constexpr int FQ = 128, FK = 64, FPP = 68;
static constexpr float SM_SCALE = 0.18033688011117310f; // (1/8) * log2(e)
static constexpr int FLASH_SMEM = (FQ * FPP * 2 + FK * FPP * 2) * 4;  // 104448 B

__global__ void __launch_bounds__(256) flash_mma_kernel()
{
    extern __shared__ float sm[];
    float* Qs = sm;                    // [128 q][68] (d in cols, tf32, pre-scaled)
    float* Ks = Qs + FQ * FPP;         // [64 kv][68] (d in cols)
    float* Vs = Ks + FK * FPP;         // [64 kv][68] (d in cols)
    float* Ps = Vs + FK * FPP;         // [128 q][68] (kv in cols)

    const int b  = blockIdx.z;
    const int h  = blockIdx.y;
    const int qt = blockIdx.x;
    const int tid  = threadIdx.x;
    const int w    = tid >> 5;
    const int lane = tid & 31;
    const int gid  = lane >> 2;   // 0..7
    const int tig  = lane & 3;    // 0..3
    const int qw   = w * 16;      // warp's q-row base inside tile

    const float* Qg = g_qp + (((size_t)b * HEADS + h) * SEQ + (size_t)qt * FQ) * DKEY;
    const float* Kg = g_kp + ((size_t)b * HEADS + h) * SEQ * DKEY;
    const float* Vg = g_vp + ((size_t)b * HEADS + h) * SEQ * DKEY;

    // Load Q tile [128][64], scale by SM_SCALE, round to tf32.
#pragma unroll
    for (int it = 0; it < 8; it++) {
        int idx = tid + it * 256;      // 0..2047
        int row = idx >> 4;            // 0..127
        int dq  = idx & 15;            // 0..15
        float4 v = *(const float4*)(Qg + (size_t)row * DKEY + dq * 4);
        v.x = to_tf32(v.x * SM_SCALE);
        v.y = to_tf32(v.y * SM_SCALE);
        v.z = to_tf32(v.z * SM_SCALE);
        v.w = to_tf32(v.w * SM_SCALE);
        *(float4*)&Qs[row * FPP + dq * 4] = v;
    }

    float o[8][4];
#pragma unroll
    for (int nt = 0; nt < 8; nt++)
#pragma unroll
        for (int r = 0; r < 4; r++) o[nt][r] = 0.0f;
    float mrun0 = -3.0e38f, mrun1 = -3.0e38f;
    float lrun0 = 0.0f, lrun1 = 0.0f;

    const int rowA0 = (qw + gid) * FPP;
    const int rowA1 = (qw + gid + 8) * FPP;

    for (int t = 0; t < SEQ / FK; t++) {
        // Load K and V tiles [64][64], tf32.
        const float* Kt = Kg + (size_t)t * FK * DKEY;
        const float* Vt = Vg + (size_t)t * FK * DKEY;
#pragma unroll
        for (int it = 0; it < 4; it++) {
            int idx = tid + it * 256;
            int row = idx >> 4;        // 0..63
            int dq  = idx & 15;
            float4 kv = *(const float4*)(Kt + (size_t)row * DKEY + dq * 4);
            kv.x = to_tf32(kv.x); kv.y = to_tf32(kv.y);
            kv.z = to_tf32(kv.z); kv.w = to_tf32(kv.w);
            *(float4*)&Ks[row * FPP + dq * 4] = kv;
            float4 vv = *(const float4*)(Vt + (size_t)row * DKEY + dq * 4);
            vv.x = to_tf32(vv.x); vv.y = to_tf32(vv.y);
            vv.z = to_tf32(vv.z); vv.w = to_tf32(vv.w);
            *(float4*)&Vs[row * FPP + dq * 4] = vv;
        }
        __syncthreads();   // K,V ready; all prior-iter reads complete

        // S = Q * K^T : warp computes [16 q][64 kv]
        float s[8][4];
#pragma unroll
        for (int nt = 0; nt < 8; nt++)
#pragma unroll
            for (int r = 0; r < 4; r++) s[nt][r] = 0.0f;

#pragma unroll
        for (int ks = 0; ks < 8; ks++) {
            const int kk = ks * 8;
            uint32_t a[4];
            a[0] = __float_as_uint(Qs[rowA0 + kk + tig]);
            a[1] = __float_as_uint(Qs[rowA1 + kk + tig]);
            a[2] = __float_as_uint(Qs[rowA0 + kk + tig + 4]);
            a[3] = __float_as_uint(Qs[rowA1 + kk + tig + 4]);
#pragma unroll
            for (int nt = 0; nt < 8; nt++) {
                uint32_t bb[2];
                bb[0] = __float_as_uint(Ks[(nt * 8 + gid) * FPP + kk + tig]);
                bb[1] = __float_as_uint(Ks[(nt * 8 + gid) * FPP + kk + tig + 4]);
                mma_tf32(s[nt], a, bb);
            }
        }

        // Online softmax for rows (qw+gid) and (qw+gid+8). Scores already in
        // log2 domain (Q pre-scaled by (1/8)*log2e).
        float mx0 = -3.0e38f, mx1 = -3.0e38f;
#pragma unroll
        for (int nt = 0; nt < 8; nt++) {
            mx0 = fmaxf(mx0, fmaxf(s[nt][0], s[nt][1]));
            mx1 = fmaxf(mx1, fmaxf(s[nt][2], s[nt][3]));
        }
        mx0 = fmaxf(mx0, __shfl_xor_sync(0xffffffffu, mx0, 1));
        mx0 = fmaxf(mx0, __shfl_xor_sync(0xffffffffu, mx0, 2));
        mx1 = fmaxf(mx1, __shfl_xor_sync(0xffffffffu, mx1, 1));
        mx1 = fmaxf(mx1, __shfl_xor_sync(0xffffffffu, mx1, 2));

        float mn0 = fmaxf(mrun0, mx0);
        float mn1 = fmaxf(mrun1, mx1);
        float c0 = fast_exp2(mrun0 - mn0);
        float c1 = fast_exp2(mrun1 - mn1);
        mrun0 = mn0; mrun1 = mn1;

        float rs0 = 0.0f, rs1 = 0.0f;
#pragma unroll
        for (int nt = 0; nt < 8; nt++) {
            float p0 = fast_exp2(s[nt][0] - mn0);
            float p1 = fast_exp2(s[nt][1] - mn0);
            float p2 = fast_exp2(s[nt][2] - mn1);
            float p3 = fast_exp2(s[nt][3] - mn1);
            rs0 += p0 + p1;
            rs1 += p2 + p3;
            *(float2*)&Ps[rowA0 + nt * 8 + tig * 2] =
                make_float2(to_tf32(p0), to_tf32(p1));
            *(float2*)&Ps[rowA1 + nt * 8 + tig * 2] =
                make_float2(to_tf32(p2), to_tf32(p3));
            o[nt][0] *= c0; o[nt][1] *= c0;
            o[nt][2] *= c1; o[nt][3] *= c1;
        }
        rs0 += __shfl_xor_sync(0xffffffffu, rs0, 1);
        rs0 += __shfl_xor_sync(0xffffffffu, rs0, 2);
        rs1 += __shfl_xor_sync(0xffffffffu, rs1, 1);
        rs1 += __shfl_xor_sync(0xffffffffu, rs1, 2);
        lrun0 = lrun0 * c0 + rs0;
        lrun1 = lrun1 * c1 + rs1;
        __syncwarp();   // P rows for this warp visible to this warp

        // O += P * V : A = Ps (own 16 rows), B = Vs read as [k=kv][n=d]
#pragma unroll
        for (int ks = 0; ks < 8; ks++) {
            const int kk = ks * 8;
            uint32_t a[4];
            a[0] = __float_as_uint(Ps[rowA0 + kk + tig]);
            a[1] = __float_as_uint(Ps[rowA1 + kk + tig]);
            a[2] = __float_as_uint(Ps[rowA0 + kk + tig + 4]);
            a[3] = __float_as_uint(Ps[rowA1 + kk + tig + 4]);
#pragma unroll
            for (int nt = 0; nt < 8; nt++) {
                uint32_t bb[2];
                bb[0] = __float_as_uint(Vs[(kk + tig) * FPP + nt * 8 + gid]);
                bb[1] = __float_as_uint(Vs[(kk + tig + 4) * FPP + nt * 8 + gid]);
                mma_tf32(o[nt], a, bb);
            }
        }
        __syncthreads();   // all K/V/P reads done before next iteration's loads
    }

    // Epilogue: normalize, write concat-head layout [B*S, H*K]
    const float inv0 = 1.0f / lrun0;
    const float inv1 = 1.0f / lrun1;
    const size_t m0 = (size_t)b * SEQ + (size_t)qt * FQ + qw + gid;
    const size_t m1 = m0 + 8;
#pragma unroll
    for (int nt = 0; nt < 8; nt++) {
        const int col = h * DKEY + nt * 8 + tig * 2;
        *(float2*)(g_ao + m0 * DMODEL + col) =
            make_float2(o[nt][0] * inv0, o[nt][1] * inv0);
        *(float2*)(g_ao + m1 * DMODEL + col) =
            make_float2(o[nt][2] * inv1, o[nt][3] * inv1);
    }
}

// ======================= launch =======================
extern "C" void kernel_launch(void* const* d_in, const int* in_sizes, int n_in,
                              void* d_out, int out_size)
{
    const float* q_in  = (const float*)d_in[0];
    const float* k_in  = (const float*)d_in[1];
    const float* v_in  = (const float*)d_in[2];
    const float* Wq    = (const float*)d_in[3];
    const float* Wk    = (const float*)d_in[4];
    const float* Wv    = (const float*)d_in[5];
    const float* Wo    = (const float*)d_in[6];
    float* out = (float*)d_out;

    float *qp, *kp, *vp, *ao;
    cudaGetSymbolAddress((void**)&qp, g_qp);
    cudaGetSymbolAddress((void**)&kp, g_kp);
    cudaGetSymbolAddress((void**)&vp, g_vp);
    cudaGetSymbolAddress((void**)&ao, g_ao);

    dim3 ggrid(DMODEL / BN, MROWS / BM);   // (8, 64)

    gemm_mma_kernel<<<ggrid, 256>>>(q_in, Wq, qp, 1);
    gemm_mma_kernel<<<ggrid, 256>>>(k_in, Wk, kp, 1);
    gemm_mma_kernel<<<ggrid, 256>>>(v_in, Wv, vp, 1);

    cudaFuncSetAttribute(flash_mma_kernel,
                         cudaFuncAttributeMaxDynamicSharedMemorySize,
                         FLASH_SMEM);
    flash_mma_kernel<<<dim3(SEQ / FQ, HEADS, BATCH), 256, FLASH_SMEM>>>();

    gemm_mma_kernel<<<ggrid, 256>>>(ao, Wo, out, 0);
}

// round 10
// speedup vs baseline: 3.2052x; 1.3840x over previous
#include <cuda_runtime.h>
#include <cstdint>
#include <cstddef>

// Problem constants
#define DMODEL 1024
#define HEADS  16
#define DKEY   64
#define BATCH  4
#define SEQ    2048
#define MROWS  (BATCH * SEQ)   // 8192

// -------- scratch (static device arrays; no allocation allowed) --------
__device__ float g_qp[(size_t)BATCH * HEADS * SEQ * DKEY];  // [B,H,S,K]
__device__ float g_kp[(size_t)BATCH * HEADS * SEQ * DKEY];
__device__ float g_vp[(size_t)BATCH * HEADS * SEQ * DKEY];
__device__ float g_ao[(size_t)MROWS * DMODEL];              // [B*S, H*K]

__device__ __forceinline__ float fast_exp2(float x) {
    float y;
    asm("ex2.approx.f32 %0, %1;" : "=f"(y) : "f"(x));
    return y;
}
__device__ __forceinline__ float to_tf32(float x) {
    float y;
    asm("cvt.rna.tf32.f32 %0, %1;" : "=f"(y) : "f"(x));
    return y;
}
__device__ __forceinline__ uint32_t smem_u32(const void* p) {
    uint32_t a;
    asm("{ .reg .u64 t; cvta.to.shared.u64 t, %1; cvt.u32.u64 %0, t; }" : "=r"(a) : "l"(p));
    return a;
}

// m16n8k8 tf32 mma: D = A(16x8,row) * B(8x8,col) + D
__device__ __forceinline__ void mma_tf32(float* c, const uint32_t* a, const uint32_t* b) {
    asm volatile(
        "mma.sync.aligned.m16n8k8.row.col.f32.tf32.tf32.f32 "
        "{%0,%1,%2,%3}, {%4,%5,%6,%7}, {%8,%9}, {%0,%1,%2,%3};"
        : "+f"(c[0]), "+f"(c[1]), "+f"(c[2]), "+f"(c[3])
        : "r"(a[0]), "r"(a[1]), "r"(a[2]), "r"(a[3]), "r"(b[0]), "r"(b[1]));
}

// ldmatrix x4 (bit-mover; used on fp32/tf32 data, 8x4-f32 tiles seen as 8x8-b16)
__device__ __forceinline__ void ldsm_x4(uint32_t* r, uint32_t addr) {
    asm volatile("ldmatrix.sync.aligned.m8n8.x4.shared.b16 {%0,%1,%2,%3}, [%4];"
                 : "=r"(r[0]), "=r"(r[1]), "=r"(r[2]), "=r"(r[3]) : "r"(addr));
}

// ============ tf32 tensor-core GEMM: C = A (M x 1024) * B^T (N x 1024) ========
// A row-major [M,1024]; B row-major [N,1024] (torch Linear weight layout).
// Block 128x128, BK=32. 8 warps in 2(M) x 4(N); warp tile 64x32.
// Smem tiles stored [row][k] pitch 36 (conflict-free for STS.128 and ldmatrix).
// mode 0: C row-major [M,1024]. mode 1: scatter to [B,H,S,K].
static constexpr int BM = 128, BN = 128, BK = 32;
static constexpr int APITCH = 36;

__global__ void __launch_bounds__(256) gemm_mma_kernel(
    const float* __restrict__ A, const float* __restrict__ B,
    float* __restrict__ C, int mode)
{
    __shared__ float As[BM * APITCH];   // [m][k]
    __shared__ float Bs[BN * APITCH];   // [n][k]

    const int tid  = threadIdx.x;
    const int wid  = tid >> 5;
    const int lane = tid & 31;
    const int gid  = lane >> 2;   // 0..7
    const int tig  = lane & 3;    // 0..3
    const int wm = (wid >> 2) * 64;   // warp M offset in block
    const int wn = (wid & 3) * 32;    // warp N offset in block
    const int bm = blockIdx.y * BM;
    const int bn = blockIdx.x * BN;

    // ldmatrix per-lane address components
    const int rA = lane & 15;             // row within 16-row A group
    const int cA = (lane >> 4) * 4;       // k offset: tiles 2,3 at +4
    const int rB = (lane & 7) + ((lane >> 4) << 3);  // row within 16-row B group
    const int cB = ((lane >> 3) & 1) * 4;
    const uint32_t As_u = smem_u32(As);
    const uint32_t Bs_u = smem_u32(Bs);

    const int ldrow = tid >> 3;           // 0..31 (+32 per it)
    const int ldkq  = tid & 7;            // 0..7

    float acc[4][4][4];
#pragma unroll
    for (int mt = 0; mt < 4; mt++)
#pragma unroll
        for (int nt = 0; nt < 4; nt++)
#pragma unroll
            for (int r = 0; r < 4; r++) acc[mt][nt][r] = 0.0f;

    // Prefetch k0 = 0
    float4 pa[4], pb[4];
#pragma unroll
    for (int it = 0; it < 4; it++) {
        int row = ldrow + it * 32;
        pa[it] = *(const float4*)(A + (size_t)(bm + row) * DMODEL + ldkq * 4);
        pb[it] = *(const float4*)(B + (size_t)(bn + row) * DMODEL + ldkq * 4);
    }

    for (int k0 = 0; k0 < DMODEL; k0 += BK) {
        // Store prefetched tile (cvt to tf32, vectorized STS)
#pragma unroll
        for (int it = 0; it < 4; it++) {
            int row = ldrow + it * 32;
            float4 va = pa[it];
            va.x = to_tf32(va.x); va.y = to_tf32(va.y);
            va.z = to_tf32(va.z); va.w = to_tf32(va.w);
            *(float4*)&As[row * APITCH + ldkq * 4] = va;
            float4 vb = pb[it];
            vb.x = to_tf32(vb.x); vb.y = to_tf32(vb.y);
            vb.z = to_tf32(vb.z); vb.w = to_tf32(vb.w);
            *(float4*)&Bs[row * APITCH + ldkq * 4] = vb;
        }
        __syncthreads();

        // Prefetch next tile while computing
        if (k0 + BK < DMODEL) {
#pragma unroll
            for (int it = 0; it < 4; it++) {
                int row = ldrow + it * 32;
                pa[it] = *(const float4*)(A + (size_t)(bm + row) * DMODEL + k0 + BK + ldkq * 4);
                pb[it] = *(const float4*)(B + (size_t)(bn + row) * DMODEL + k0 + BK + ldkq * 4);
            }
        }

#pragma unroll
        for (int ks = 0; ks < 4; ks++) {
            const int kk = ks * 8;
            uint32_t av[4][4], bv[2][4];
#pragma unroll
            for (int mt = 0; mt < 4; mt++)
                ldsm_x4(av[mt], As_u + 4u * ((wm + mt * 16 + rA) * APITCH + kk + cA));
#pragma unroll
            for (int np = 0; np < 2; np++)
                ldsm_x4(bv[np], Bs_u + 4u * ((wn + np * 16 + rB) * APITCH + kk + cB));
#pragma unroll
            for (int mt = 0; mt < 4; mt++)
#pragma unroll
                for (int np = 0; np < 2; np++) {
                    mma_tf32(acc[mt][2 * np],     av[mt], &bv[np][0]);
                    mma_tf32(acc[mt][2 * np + 1], av[mt], &bv[np][2]);
                }
        }
        __syncthreads();
    }

    // Epilogue
#pragma unroll
    for (int mt = 0; mt < 4; mt++) {
        const int r0 = bm + wm + mt * 16 + gid;
#pragma unroll
        for (int half = 0; half < 2; half++) {
            const int r = r0 + half * 8;
            const int b = r >> 11;            // r / SEQ
            const int s = r & (SEQ - 1);
#pragma unroll
            for (int nt = 0; nt < 4; nt++) {
                const int col = bn + wn + nt * 8 + tig * 2;
                float2 v = make_float2(acc[mt][nt][half * 2],
                                       acc[mt][nt][half * 2 + 1]);
                if (mode == 0) {
                    *(float2*)(C + (size_t)r * DMODEL + col) = v;
                } else {
                    const int h  = col >> 6;
                    const int kk = col & (DKEY - 1);
                    *(float2*)(C + ((((size_t)b * HEADS + h) * SEQ) + s) * DKEY + kk) = v;
                }
            }
        }
    }
}

// ======================= Flash attention (tf32 mma.sync) =======================
// CTA: 128 queries x full sequence, KV tiles of 64. 8 warps; warp w owns q rows
// [w*16, w*16+16). All matmuls on tensor cores (m16n8k8 tf32).
static constexpr int FQ = 128, FK = 64, FPP = 68;
static constexpr float SM_SCALE = 0.18033688011117310f; // (1/8) * log2(e)
static constexpr int FLASH_SMEM = (FQ * FPP * 2 + FK * FPP * 2) * 4;  // 104448 B

__global__ void __launch_bounds__(256) flash_mma_kernel()
{
    extern __shared__ float sm[];
    float* Qs = sm;                    // [128 q][68] (d in cols, tf32, pre-scaled)
    float* Ks = Qs + FQ * FPP;         // [64 kv][68] (d in cols)
    float* Vs = Ks + FK * FPP;         // [64 kv][68] (d in cols)
    float* Ps = Vs + FK * FPP;         // [128 q][68] (kv in cols)

    const int b  = blockIdx.z;
    const int h  = blockIdx.y;
    const int qt = blockIdx.x;
    const int tid  = threadIdx.x;
    const int w    = tid >> 5;
    const int lane = tid & 31;
    const int gid  = lane >> 2;   // 0..7
    const int tig  = lane & 3;    // 0..3
    const int qw   = w * 16;      // warp's q-row base inside tile

    const float* Qg = g_qp + (((size_t)b * HEADS + h) * SEQ + (size_t)qt * FQ) * DKEY;
    const float* Kg = g_kp + ((size_t)b * HEADS + h) * SEQ * DKEY;
    const float* Vg = g_vp + ((size_t)b * HEADS + h) * SEQ * DKEY;

    // Load Q tile [128][64], scale by SM_SCALE, round to tf32.
#pragma unroll
    for (int it = 0; it < 8; it++) {
        int idx = tid + it * 256;      // 0..2047
        int row = idx >> 4;            // 0..127
        int dq  = idx & 15;            // 0..15
        float4 v = *(const float4*)(Qg + (size_t)row * DKEY + dq * 4);
        v.x = to_tf32(v.x * SM_SCALE);
        v.y = to_tf32(v.y * SM_SCALE);
        v.z = to_tf32(v.z * SM_SCALE);
        v.w = to_tf32(v.w * SM_SCALE);
        *(float4*)&Qs[row * FPP + dq * 4] = v;
    }

    float o[8][4];
#pragma unroll
    for (int nt = 0; nt < 8; nt++)
#pragma unroll
        for (int r = 0; r < 4; r++) o[nt][r] = 0.0f;
    float mrun0 = -3.0e38f, mrun1 = -3.0e38f;
    float lrun0 = 0.0f, lrun1 = 0.0f;

    const int rowA0 = (qw + gid) * FPP;
    const int rowA1 = (qw + gid + 8) * FPP;

    for (int t = 0; t < SEQ / FK; t++) {
        // Load K and V tiles [64][64], tf32.
        const float* Kt = Kg + (size_t)t * FK * DKEY;
        const float* Vt = Vg + (size_t)t * FK * DKEY;
#pragma unroll
        for (int it = 0; it < 4; it++) {
            int idx = tid + it * 256;
            int row = idx >> 4;        // 0..63
            int dq  = idx & 15;
            float4 kv = *(const float4*)(Kt + (size_t)row * DKEY + dq * 4);
            kv.x = to_tf32(kv.x); kv.y = to_tf32(kv.y);
            kv.z = to_tf32(kv.z); kv.w = to_tf32(kv.w);
            *(float4*)&Ks[row * FPP + dq * 4] = kv;
            float4 vv = *(const float4*)(Vt + (size_t)row * DKEY + dq * 4);
            vv.x = to_tf32(vv.x); vv.y = to_tf32(vv.y);
            vv.z = to_tf32(vv.z); vv.w = to_tf32(vv.w);
            *(float4*)&Vs[row * FPP + dq * 4] = vv;
        }
        __syncthreads();   // K,V ready; all prior-iter reads complete

        // S = Q * K^T : warp computes [16 q][64 kv]
        float s[8][4];
#pragma unroll
        for (int nt = 0; nt < 8; nt++)
#pragma unroll
            for (int r = 0; r < 4; r++) s[nt][r] = 0.0f;

#pragma unroll
        for (int ks = 0; ks < 8; ks++) {
            const int kk = ks * 8;
            uint32_t a[4];
            a[0] = __float_as_uint(Qs[rowA0 + kk + tig]);
            a[1] = __float_as_uint(Qs[rowA1 + kk + tig]);
            a[2] = __float_as_uint(Qs[rowA0 + kk + tig + 4]);
            a[3] = __float_as_uint(Qs[rowA1 + kk + tig + 4]);
#pragma unroll
            for (int nt = 0; nt < 8; nt++) {
                uint32_t bb[2];
                bb[0] = __float_as_uint(Ks[(nt * 8 + gid) * FPP + kk + tig]);
                bb[1] = __float_as_uint(Ks[(nt * 8 + gid) * FPP + kk + tig + 4]);
                mma_tf32(s[nt], a, bb);
            }
        }

        // Online softmax for rows (qw+gid) and (qw+gid+8). Scores already in
        // log2 domain (Q pre-scaled by (1/8)*log2e).
        float mx0 = -3.0e38f, mx1 = -3.0e38f;
#pragma unroll
        for (int nt = 0; nt < 8; nt++) {
            mx0 = fmaxf(mx0, fmaxf(s[nt][0], s[nt][1]));
            mx1 = fmaxf(mx1, fmaxf(s[nt][2], s[nt][3]));
        }
        mx0 = fmaxf(mx0, __shfl_xor_sync(0xffffffffu, mx0, 1));
        mx0 = fmaxf(mx0, __shfl_xor_sync(0xffffffffu, mx0, 2));
        mx1 = fmaxf(mx1, __shfl_xor_sync(0xffffffffu, mx1, 1));
        mx1 = fmaxf(mx1, __shfl_xor_sync(0xffffffffu, mx1, 2));

        float mn0 = fmaxf(mrun0, mx0);
        float mn1 = fmaxf(mrun1, mx1);
        float c0 = fast_exp2(mrun0 - mn0);
        float c1 = fast_exp2(mrun1 - mn1);
        mrun0 = mn0; mrun1 = mn1;

        float rs0 = 0.0f, rs1 = 0.0f;
#pragma unroll
        for (int nt = 0; nt < 8; nt++) {
            float p0 = fast_exp2(s[nt][0] - mn0);
            float p1 = fast_exp2(s[nt][1] - mn0);
            float p2 = fast_exp2(s[nt][2] - mn1);
            float p3 = fast_exp2(s[nt][3] - mn1);
            rs0 += p0 + p1;
            rs1 += p2 + p3;
            *(float2*)&Ps[rowA0 + nt * 8 + tig * 2] =
                make_float2(to_tf32(p0), to_tf32(p1));
            *(float2*)&Ps[rowA1 + nt * 8 + tig * 2] =
                make_float2(to_tf32(p2), to_tf32(p3));
            o[nt][0] *= c0; o[nt][1] *= c0;
            o[nt][2] *= c1; o[nt][3] *= c1;
        }
        rs0 += __shfl_xor_sync(0xffffffffu, rs0, 1);
        rs0 += __shfl_xor_sync(0xffffffffu, rs0, 2);
        rs1 += __shfl_xor_sync(0xffffffffu, rs1, 1);
        rs1 += __shfl_xor_sync(0xffffffffu, rs1, 2);
        lrun0 = lrun0 * c0 + rs0;
        lrun1 = lrun1 * c1 + rs1;
        __syncwarp();   // P rows for this warp visible to this warp

        // O += P * V : A = Ps (own 16 rows), B = Vs read as [k=kv][n=d]
#pragma unroll
        for (int ks = 0; ks < 8; ks++) {
            const int kk = ks * 8;
            uint32_t a[4];
            a[0] = __float_as_uint(Ps[rowA0 + kk + tig]);
            a[1] = __float_as_uint(Ps[rowA1 + kk + tig]);
            a[2] = __float_as_uint(Ps[rowA0 + kk + tig + 4]);
            a[3] = __float_as_uint(Ps[rowA1 + kk + tig + 4]);
#pragma unroll
            for (int nt = 0; nt < 8; nt++) {
                uint32_t bb[2];
                bb[0] = __float_as_uint(Vs[(kk + tig) * FPP + nt * 8 + gid]);
                bb[1] = __float_as_uint(Vs[(kk + tig + 4) * FPP + nt * 8 + gid]);
                mma_tf32(o[nt], a, bb);
            }
        }
        __syncthreads();   // all K/V/P reads done before next iteration's loads
    }

    // Epilogue: normalize, write concat-head layout [B*S, H*K]
    const float inv0 = 1.0f / lrun0;
    const float inv1 = 1.0f / lrun1;
    const size_t m0 = (size_t)b * SEQ + (size_t)qt * FQ + qw + gid;
    const size_t m1 = m0 + 8;
#pragma unroll
    for (int nt = 0; nt < 8; nt++) {
        const int col = h * DKEY + nt * 8 + tig * 2;
        *(float2*)(g_ao + m0 * DMODEL + col) =
            make_float2(o[nt][0] * inv0, o[nt][1] * inv0);
        *(float2*)(g_ao + m1 * DMODEL + col) =
            make_float2(o[nt][2] * inv1, o[nt][3] * inv1);
    }
}

// ======================= launch =======================
extern "C" void kernel_launch(void* const* d_in, const int* in_sizes, int n_in,
                              void* d_out, int out_size)
{
    const float* q_in  = (const float*)d_in[0];
    const float* k_in  = (const float*)d_in[1];
    const float* v_in  = (const float*)d_in[2];
    const float* Wq    = (const float*)d_in[3];
    const float* Wk    = (const float*)d_in[4];
    const float* Wv    = (const float*)d_in[5];
    const float* Wo    = (const float*)d_in[6];
    float* out = (float*)d_out;

    float *qp, *kp, *vp, *ao;
    cudaGetSymbolAddress((void**)&qp, g_qp);
    cudaGetSymbolAddress((void**)&kp, g_kp);
    cudaGetSymbolAddress((void**)&vp, g_vp);
    cudaGetSymbolAddress((void**)&ao, g_ao);

    dim3 ggrid(DMODEL / BN, MROWS / BM);   // (8, 64)

    gemm_mma_kernel<<<ggrid, 256>>>(q_in, Wq, qp, 1);
    gemm_mma_kernel<<<ggrid, 256>>>(k_in, Wk, kp, 1);
    gemm_mma_kernel<<<ggrid, 256>>>(v_in, Wv, vp, 1);

    cudaFuncSetAttribute(flash_mma_kernel,
                         cudaFuncAttributeMaxDynamicSharedMemorySize,
                         FLASH_SMEM);
    flash_mma_kernel<<<dim3(SEQ / FQ, HEADS, BATCH), 256, FLASH_SMEM>>>();

    gemm_mma_kernel<<<ggrid, 256>>>(ao, Wo, out, 0);
}

// round 11
// speedup vs baseline: 3.2898x; 1.0264x over previous
#include <cuda_runtime.h>
#include <cstdint>
#include <cstddef>

// Problem constants
#define DMODEL 1024
#define HEADS  16
#define DKEY   64
#define BATCH  4
#define SEQ    2048
#define MROWS  (BATCH * SEQ)   // 8192

// -------- scratch (static device arrays; no allocation allowed) --------
__device__ float g_qp[(size_t)BATCH * HEADS * SEQ * DKEY];  // [B,H,S,K]
__device__ float g_kp[(size_t)BATCH * HEADS * SEQ * DKEY];
__device__ float g_vp[(size_t)BATCH * HEADS * SEQ * DKEY];
__device__ float g_ao[(size_t)MROWS * DMODEL];              // [B*S, H*K]

__device__ __forceinline__ float fast_exp2(float x) {
    float y;
    asm("ex2.approx.f32 %0, %1;" : "=f"(y) : "f"(x));
    return y;
}
__device__ __forceinline__ float to_tf32(float x) {
    float y;
    asm("cvt.rna.tf32.f32 %0, %1;" : "=f"(y) : "f"(x));
    return y;
}
__device__ __forceinline__ uint32_t smem_u32(const void* p) {
    uint32_t a;
    asm("{ .reg .u64 t; cvta.to.shared.u64 t, %1; cvt.u32.u64 %0, t; }" : "=r"(a) : "l"(p));
    return a;
}

// m16n8k8 tf32 mma: D = A(16x8,row) * B(8x8,col) + D
__device__ __forceinline__ void mma_tf32(float* c, const uint32_t* a, const uint32_t* b) {
    asm volatile(
        "mma.sync.aligned.m16n8k8.row.col.f32.tf32.tf32.f32 "
        "{%0,%1,%2,%3}, {%4,%5,%6,%7}, {%8,%9}, {%0,%1,%2,%3};"
        : "+f"(c[0]), "+f"(c[1]), "+f"(c[2]), "+f"(c[3])
        : "r"(a[0]), "r"(a[1]), "r"(a[2]), "r"(a[3]), "r"(b[0]), "r"(b[1]));
}

// ldmatrix x4 (bit-mover; fp32/tf32 data, 8x4-f32 tiles seen as 8x8-b16)
__device__ __forceinline__ void ldsm_x4(uint32_t* r, uint32_t addr) {
    asm volatile("ldmatrix.sync.aligned.m8n8.x4.shared.b16 {%0,%1,%2,%3}, [%4];"
                 : "=r"(r[0]), "=r"(r[1]), "=r"(r[2]), "=r"(r[3]) : "r"(addr));
}

// ============ tf32 tensor-core GEMM: C = A (M x 1024) * B^T (N x 1024) ========
static constexpr int BM = 128, BN = 128, BK = 32;
static constexpr int APITCH = 36;

__global__ void __launch_bounds__(256) gemm_mma_kernel(
    const float* __restrict__ A, const float* __restrict__ B,
    float* __restrict__ C, int mode)
{
    __shared__ float As[BM * APITCH];   // [m][k]
    __shared__ float Bs[BN * APITCH];   // [n][k]

    const int tid  = threadIdx.x;
    const int wid  = tid >> 5;
    const int lane = tid & 31;
    const int gid  = lane >> 2;   // 0..7
    const int tig  = lane & 3;    // 0..3
    const int wm = (wid >> 2) * 64;
    const int wn = (wid & 3) * 32;
    const int bm = blockIdx.y * BM;
    const int bn = blockIdx.x * BN;

    const int rA = lane & 15;
    const int cA = (lane >> 4) * 4;
    const int rB = (lane & 7) + ((lane >> 4) << 3);
    const int cB = ((lane >> 3) & 1) * 4;
    const uint32_t As_u = smem_u32(As);
    const uint32_t Bs_u = smem_u32(Bs);

    const int ldrow = tid >> 3;
    const int ldkq  = tid & 7;

    float acc[4][4][4];
#pragma unroll
    for (int mt = 0; mt < 4; mt++)
#pragma unroll
        for (int nt = 0; nt < 4; nt++)
#pragma unroll
            for (int r = 0; r < 4; r++) acc[mt][nt][r] = 0.0f;

    float4 pa[4], pb[4];
#pragma unroll
    for (int it = 0; it < 4; it++) {
        int row = ldrow + it * 32;
        pa[it] = *(const float4*)(A + (size_t)(bm + row) * DMODEL + ldkq * 4);
        pb[it] = *(const float4*)(B + (size_t)(bn + row) * DMODEL + ldkq * 4);
    }

    for (int k0 = 0; k0 < DMODEL; k0 += BK) {
#pragma unroll
        for (int it = 0; it < 4; it++) {
            int row = ldrow + it * 32;
            float4 va = pa[it];
            va.x = to_tf32(va.x); va.y = to_tf32(va.y);
            va.z = to_tf32(va.z); va.w = to_tf32(va.w);
            *(float4*)&As[row * APITCH + ldkq * 4] = va;
            float4 vb = pb[it];
            vb.x = to_tf32(vb.x); vb.y = to_tf32(vb.y);
            vb.z = to_tf32(vb.z); vb.w = to_tf32(vb.w);
            *(float4*)&Bs[row * APITCH + ldkq * 4] = vb;
        }
        __syncthreads();

        if (k0 + BK < DMODEL) {
#pragma unroll
            for (int it = 0; it < 4; it++) {
                int row = ldrow + it * 32;
                pa[it] = *(const float4*)(A + (size_t)(bm + row) * DMODEL + k0 + BK + ldkq * 4);
                pb[it] = *(const float4*)(B + (size_t)(bn + row) * DMODEL + k0 + BK + ldkq * 4);
            }
        }

#pragma unroll
        for (int ks = 0; ks < 4; ks++) {
            const int kk = ks * 8;
            uint32_t av[4][4], bv[2][4];
#pragma unroll
            for (int mt = 0; mt < 4; mt++)
                ldsm_x4(av[mt], As_u + 4u * ((wm + mt * 16 + rA) * APITCH + kk + cA));
#pragma unroll
            for (int np = 0; np < 2; np++)
                ldsm_x4(bv[np], Bs_u + 4u * ((wn + np * 16 + rB) * APITCH + kk + cB));
#pragma unroll
            for (int mt = 0; mt < 4; mt++)
#pragma unroll
                for (int np = 0; np < 2; np++) {
                    mma_tf32(acc[mt][2 * np],     av[mt], &bv[np][0]);
                    mma_tf32(acc[mt][2 * np + 1], av[mt], &bv[np][2]);
                }
        }
        __syncthreads();
    }

#pragma unroll
    for (int mt = 0; mt < 4; mt++) {
        const int r0 = bm + wm + mt * 16 + gid;
#pragma unroll
        for (int half = 0; half < 2; half++) {
            const int r = r0 + half * 8;
            const int b = r >> 11;
            const int s = r & (SEQ - 1);
#pragma unroll
            for (int nt = 0; nt < 4; nt++) {
                const int col = bn + wn + nt * 8 + tig * 2;
                float2 v = make_float2(acc[mt][nt][half * 2],
                                       acc[mt][nt][half * 2 + 1]);
                if (mode == 0) {
                    *(float2*)(C + (size_t)r * DMODEL + col) = v;
                } else {
                    const int h  = col >> 6;
                    const int kk = col & (DKEY - 1);
                    *(float2*)(C + ((((size_t)b * HEADS + h) * SEQ) + s) * DKEY + kk) = v;
                }
            }
        }
    }
}

// ======================= Flash attention (tf32 mma.sync + ldmatrix) ===========
// CTA: 128 queries x full sequence, KV tiles of 64. 8 warps; warp w owns q rows
// [w*16, w*16+16). All fragments via ldmatrix; V stored transposed [d][kv].
static constexpr int FQ = 128, FK = 64, FPP = 68;
static constexpr float SM_SCALE = 0.18033688011117310f; // (1/8) * log2(e)
static constexpr int FLASH_SMEM = (FQ * FPP * 2 + FK * FPP * 2) * 4;  // 104448 B

__global__ void __launch_bounds__(256, 2) flash_mma_kernel()
{
    extern __shared__ float sm[];
    float* Qs = sm;                    // [128 q][68]  (d in cols, tf32, pre-scaled)
    float* Ks = Qs + FQ * FPP;         // [64 kv][68]  (d in cols)  == B [n][k]
    float* Vt = Ks + FK * FPP;         // [64 d][68]   (kv in cols) == B [n][k]
    float* Ps = Vt + FK * FPP;         // [128 q][68]  (kv in cols)

    const int b  = blockIdx.z;
    const int h  = blockIdx.y;
    const int qt = blockIdx.x;
    const int tid  = threadIdx.x;
    const int w    = tid >> 5;
    const int lane = tid & 31;
    const int gid  = lane >> 2;   // 0..7
    const int tig  = lane & 3;    // 0..3
    const int qw   = w * 16;      // warp's q-row base inside tile

    // ldmatrix lane-address components (same mapping as GEMM, verified)
    const int rA = lane & 15;
    const int cA = (lane >> 4) * 4;
    const int rB = (lane & 7) + ((lane >> 4) << 3);
    const int cB = ((lane >> 3) & 1) * 4;
    const uint32_t Qs_u = smem_u32(Qs);
    const uint32_t Ks_u = smem_u32(Ks);
    const uint32_t Vt_u = smem_u32(Vt);
    const uint32_t Ps_u = smem_u32(Ps);

    const float* Qg = g_qp + (((size_t)b * HEADS + h) * SEQ + (size_t)qt * FQ) * DKEY;
    const float* Kg = g_kp + ((size_t)b * HEADS + h) * SEQ * DKEY;
    const float* Vg = g_vp + ((size_t)b * HEADS + h) * SEQ * DKEY;

    // Load Q tile [128][64], scale by SM_SCALE, round to tf32.
#pragma unroll
    for (int it = 0; it < 8; it++) {
        int idx = tid + it * 256;      // 0..2047
        int row = idx >> 4;            // 0..127
        int dq  = idx & 15;            // 0..15
        float4 v = *(const float4*)(Qg + (size_t)row * DKEY + dq * 4);
        v.x = to_tf32(v.x * SM_SCALE);
        v.y = to_tf32(v.y * SM_SCALE);
        v.z = to_tf32(v.z * SM_SCALE);
        v.w = to_tf32(v.w * SM_SCALE);
        *(float4*)&Qs[row * FPP + dq * 4] = v;
    }

    float o[8][4];
#pragma unroll
    for (int nt = 0; nt < 8; nt++)
#pragma unroll
        for (int r = 0; r < 4; r++) o[nt][r] = 0.0f;
    float mrun0 = -3.0e38f, mrun1 = -3.0e38f;
    float lrun0 = 0.0f, lrun1 = 0.0f;

    const int rowA0 = (qw + gid) * FPP;
    const int rowA1 = (qw + gid + 8) * FPP;

    for (int t = 0; t < SEQ / FK; t++) {
        const float* Kt = Kg + (size_t)t * FK * DKEY;
        const float* Vtg = Vg + (size_t)t * FK * DKEY;
        // K tile [64 kv][64 d] -> Ks[kv][d]  (vectorized)
#pragma unroll
        for (int it = 0; it < 4; it++) {
            int idx = tid + it * 256;
            int row = idx >> 4;        // kv 0..63
            int dq  = idx & 15;
            float4 kv = *(const float4*)(Kt + (size_t)row * DKEY + dq * 4);
            kv.x = to_tf32(kv.x); kv.y = to_tf32(kv.y);
            kv.z = to_tf32(kv.z); kv.w = to_tf32(kv.w);
            *(float4*)&Ks[row * FPP + dq * 4] = kv;
        }
        // V tile transposed -> Vt[d][kv]. Thread -> (dq, kv): STS banks = const+kv
        // within a warp => conflict-free scalar stores.
#pragma unroll
        for (int it = 0; it < 4; it++) {
            int idx = tid + it * 256;  // 0..1023
            int kv  = idx & 63;        // kv row in gmem
            int dq  = idx >> 6;        // 0..15 d-quad
            float4 vv = *(const float4*)(Vtg + (size_t)kv * DKEY + dq * 4);
            Vt[(dq * 4 + 0) * FPP + kv] = to_tf32(vv.x);
            Vt[(dq * 4 + 1) * FPP + kv] = to_tf32(vv.y);
            Vt[(dq * 4 + 2) * FPP + kv] = to_tf32(vv.z);
            Vt[(dq * 4 + 3) * FPP + kv] = to_tf32(vv.w);
        }
        __syncthreads();   // K,V ready; all prior-iter reads complete

        // S = Q * K^T : warp computes [16 q][64 kv], all fragments via ldmatrix
        float s[8][4];
#pragma unroll
        for (int nt = 0; nt < 8; nt++)
#pragma unroll
            for (int r = 0; r < 4; r++) s[nt][r] = 0.0f;

#pragma unroll
        for (int ks = 0; ks < 8; ks++) {
            const int kk = ks * 8;
            uint32_t a[4];
            ldsm_x4(a, Qs_u + 4u * ((qw + rA) * FPP + kk + cA));
#pragma unroll
            for (int g = 0; g < 4; g++) {
                uint32_t bv[4];
                ldsm_x4(bv, Ks_u + 4u * ((g * 16 + rB) * FPP + kk + cB));
                mma_tf32(s[2 * g],     a, &bv[0]);
                mma_tf32(s[2 * g + 1], a, &bv[2]);
            }
        }

        // Online softmax (log2 domain; Q pre-scaled by (1/8)*log2e).
        float mx0 = -3.0e38f, mx1 = -3.0e38f;
#pragma unroll
        for (int nt = 0; nt < 8; nt++) {
            mx0 = fmaxf(mx0, fmaxf(s[nt][0], s[nt][1]));
            mx1 = fmaxf(mx1, fmaxf(s[nt][2], s[nt][3]));
        }
        mx0 = fmaxf(mx0, __shfl_xor_sync(0xffffffffu, mx0, 1));
        mx0 = fmaxf(mx0, __shfl_xor_sync(0xffffffffu, mx0, 2));
        mx1 = fmaxf(mx1, __shfl_xor_sync(0xffffffffu, mx1, 1));
        mx1 = fmaxf(mx1, __shfl_xor_sync(0xffffffffu, mx1, 2));

        float mn0 = fmaxf(mrun0, mx0);
        float mn1 = fmaxf(mrun1, mx1);
        float c0 = fast_exp2(mrun0 - mn0);
        float c1 = fast_exp2(mrun1 - mn1);
        mrun0 = mn0; mrun1 = mn1;

        float rs0 = 0.0f, rs1 = 0.0f;
#pragma unroll
        for (int nt = 0; nt < 8; nt++) {
            float p0 = fast_exp2(s[nt][0] - mn0);
            float p1 = fast_exp2(s[nt][1] - mn0);
            float p2 = fast_exp2(s[nt][2] - mn1);
            float p3 = fast_exp2(s[nt][3] - mn1);
            rs0 += p0 + p1;
            rs1 += p2 + p3;
            *(float2*)&Ps[rowA0 + nt * 8 + tig * 2] =
                make_float2(to_tf32(p0), to_tf32(p1));
            *(float2*)&Ps[rowA1 + nt * 8 + tig * 2] =
                make_float2(to_tf32(p2), to_tf32(p3));
            o[nt][0] *= c0; o[nt][1] *= c0;
            o[nt][2] *= c1; o[nt][3] *= c1;
        }
        rs0 += __shfl_xor_sync(0xffffffffu, rs0, 1);
        rs0 += __shfl_xor_sync(0xffffffffu, rs0, 2);
        rs1 += __shfl_xor_sync(0xffffffffu, rs1, 1);
        rs1 += __shfl_xor_sync(0xffffffffu, rs1, 2);
        lrun0 = lrun0 * c0 + rs0;
        lrun1 = lrun1 * c1 + rs1;
        __syncwarp();   // this warp's P rows visible to this warp

        // O += P * V : A = Ps rows (ldmatrix), B = Vt rows (ldmatrix)
#pragma unroll
        for (int ks = 0; ks < 8; ks++) {
            const int kk = ks * 8;
            uint32_t a[4];
            ldsm_x4(a, Ps_u + 4u * ((qw + rA) * FPP + kk + cA));
#pragma unroll
            for (int g = 0; g < 4; g++) {
                uint32_t bv[4];
                ldsm_x4(bv, Vt_u + 4u * ((g * 16 + rB) * FPP + kk + cB));
                mma_tf32(o[2 * g],     a, &bv[0]);
                mma_tf32(o[2 * g + 1], a, &bv[2]);
            }
        }
        __syncthreads();   // all K/V/P reads done before next iteration's loads
    }

    // Epilogue: normalize, write concat-head layout [B*S, H*K]
    const float inv0 = 1.0f / lrun0;
    const float inv1 = 1.0f / lrun1;
    const size_t m0 = (size_t)b * SEQ + (size_t)qt * FQ + qw + gid;
    const size_t m1 = m0 + 8;
#pragma unroll
    for (int nt = 0; nt < 8; nt++) {
        const int col = h * DKEY + nt * 8 + tig * 2;
        *(float2*)(g_ao + m0 * DMODEL + col) =
            make_float2(o[nt][0] * inv0, o[nt][1] * inv0);
        *(float2*)(g_ao + m1 * DMODEL + col) =
            make_float2(o[nt][2] * inv1, o[nt][3] * inv1);
    }
}

// ======================= launch =======================
extern "C" void kernel_launch(void* const* d_in, const int* in_sizes, int n_in,
                              void* d_out, int out_size)
{
    const float* q_in  = (const float*)d_in[0];
    const float* k_in  = (const float*)d_in[1];
    const float* v_in  = (const float*)d_in[2];
    const float* Wq    = (const float*)d_in[3];
    const float* Wk    = (const float*)d_in[4];
    const float* Wv    = (const float*)d_in[5];
    const float* Wo    = (const float*)d_in[6];
    float* out = (float*)d_out;

    float *qp, *kp, *vp, *ao;
    cudaGetSymbolAddress((void**)&qp, g_qp);
    cudaGetSymbolAddress((void**)&kp, g_kp);
    cudaGetSymbolAddress((void**)&vp, g_vp);
    cudaGetSymbolAddress((void**)&ao, g_ao);

    dim3 ggrid(DMODEL / BN, MROWS / BM);   // (8, 64)

    gemm_mma_kernel<<<ggrid, 256>>>(q_in, Wq, qp, 1);
    gemm_mma_kernel<<<ggrid, 256>>>(k_in, Wk, kp, 1);
    gemm_mma_kernel<<<ggrid, 256>>>(v_in, Wv, vp, 1);

    cudaFuncSetAttribute(flash_mma_kernel,
                         cudaFuncAttributeMaxDynamicSharedMemorySize,
                         FLASH_SMEM);
    flash_mma_kernel<<<dim3(SEQ / FQ, HEADS, BATCH), 256, FLASH_SMEM>>>();

    gemm_mma_kernel<<<ggrid, 256>>>(ao, Wo, out, 0);
}

// round 12
// speedup vs baseline: 3.4741x; 1.0560x over previous
#include <cuda_runtime.h>
#include <cstdint>
#include <cstddef>

// Problem constants
#define DMODEL 1024
#define HEADS  16
#define DKEY   64
#define BATCH  4
#define SEQ    2048
#define MROWS  (BATCH * SEQ)   // 8192

// -------- scratch (static device arrays; no allocation allowed) --------
__device__ float g_qp[(size_t)BATCH * HEADS * SEQ * DKEY];  // [B,H,S,K]
__device__ float g_kp[(size_t)BATCH * HEADS * SEQ * DKEY];
__device__ float g_vp[(size_t)BATCH * HEADS * SEQ * DKEY];
__device__ float g_ao[(size_t)MROWS * DMODEL];              // [B*S, H*K]

__device__ __forceinline__ float fast_exp2(float x) {
    float y;
    asm("ex2.approx.f32 %0, %1;" : "=f"(y) : "f"(x));
    return y;
}
__device__ __forceinline__ float to_tf32(float x) {
    float y;
    asm("cvt.rna.tf32.f32 %0, %1;" : "=f"(y) : "f"(x));
    return y;
}
__device__ __forceinline__ uint32_t smem_u32(const void* p) {
    uint32_t a;
    asm("{ .reg .u64 t; cvta.to.shared.u64 t, %1; cvt.u32.u64 %0, t; }" : "=r"(a) : "l"(p));
    return a;
}

// m16n8k8 tf32 mma: D = A(16x8,row) * B(8x8,col) + D
__device__ __forceinline__ void mma_tf32(float* c, const uint32_t* a, const uint32_t* b) {
    asm volatile(
        "mma.sync.aligned.m16n8k8.row.col.f32.tf32.tf32.f32 "
        "{%0,%1,%2,%3}, {%4,%5,%6,%7}, {%8,%9}, {%0,%1,%2,%3};"
        : "+f"(c[0]), "+f"(c[1]), "+f"(c[2]), "+f"(c[3])
        : "r"(a[0]), "r"(a[1]), "r"(a[2]), "r"(a[3]), "r"(b[0]), "r"(b[1]));
}

// ldmatrix x4 (bit-mover; fp32/tf32 data, 8x4-f32 tiles seen as 8x8-b16)
__device__ __forceinline__ void ldsm_x4(uint32_t* r, uint32_t addr) {
    asm volatile("ldmatrix.sync.aligned.m8n8.x4.shared.b16 {%0,%1,%2,%3}, [%4];"
                 : "=r"(r[0]), "=r"(r[1]), "=r"(r[2]), "=r"(r[3]) : "r"(addr));
}

// ============ tf32 tensor-core GEMM: C = A (M x 1024) * B^T (N x 1024) ========
static constexpr int BM = 128, BN = 128, BK = 32;
static constexpr int APITCH = 36;

__global__ void __launch_bounds__(256) gemm_mma_kernel(
    const float* __restrict__ A, const float* __restrict__ B,
    float* __restrict__ C, int mode)
{
    __shared__ float As[BM * APITCH];   // [m][k]
    __shared__ float Bs[BN * APITCH];   // [n][k]

    const int tid  = threadIdx.x;
    const int wid  = tid >> 5;
    const int lane = tid & 31;
    const int gid  = lane >> 2;   // 0..7
    const int tig  = lane & 3;    // 0..3
    const int wm = (wid >> 2) * 64;
    const int wn = (wid & 3) * 32;
    const int bm = blockIdx.y * BM;
    const int bn = blockIdx.x * BN;

    const int rA = lane & 15;
    const int cA = (lane >> 4) * 4;
    const int rB = (lane & 7) + ((lane >> 4) << 3);
    const int cB = ((lane >> 3) & 1) * 4;
    const uint32_t As_u = smem_u32(As);
    const uint32_t Bs_u = smem_u32(Bs);

    const int ldrow = tid >> 3;
    const int ldkq  = tid & 7;

    float acc[4][4][4];
#pragma unroll
    for (int mt = 0; mt < 4; mt++)
#pragma unroll
        for (int nt = 0; nt < 4; nt++)
#pragma unroll
            for (int r = 0; r < 4; r++) acc[mt][nt][r] = 0.0f;

    float4 pa[4], pb[4];
#pragma unroll
    for (int it = 0; it < 4; it++) {
        int row = ldrow + it * 32;
        pa[it] = *(const float4*)(A + (size_t)(bm + row) * DMODEL + ldkq * 4);
        pb[it] = *(const float4*)(B + (size_t)(bn + row) * DMODEL + ldkq * 4);
    }

    for (int k0 = 0; k0 < DMODEL; k0 += BK) {
#pragma unroll
        for (int it = 0; it < 4; it++) {
            int row = ldrow + it * 32;
            float4 va = pa[it];
            va.x = to_tf32(va.x); va.y = to_tf32(va.y);
            va.z = to_tf32(va.z); va.w = to_tf32(va.w);
            *(float4*)&As[row * APITCH + ldkq * 4] = va;
            float4 vb = pb[it];
            vb.x = to_tf32(vb.x); vb.y = to_tf32(vb.y);
            vb.z = to_tf32(vb.z); vb.w = to_tf32(vb.w);
            *(float4*)&Bs[row * APITCH + ldkq * 4] = vb;
        }
        __syncthreads();

        if (k0 + BK < DMODEL) {
#pragma unroll
            for (int it = 0; it < 4; it++) {
                int row = ldrow + it * 32;
                pa[it] = *(const float4*)(A + (size_t)(bm + row) * DMODEL + k0 + BK + ldkq * 4);
                pb[it] = *(const float4*)(B + (size_t)(bn + row) * DMODEL + k0 + BK + ldkq * 4);
            }
        }

#pragma unroll
        for (int ks = 0; ks < 4; ks++) {
            const int kk = ks * 8;
            uint32_t av[4][4], bv[2][4];
#pragma unroll
            for (int mt = 0; mt < 4; mt++)
                ldsm_x4(av[mt], As_u + 4u * ((wm + mt * 16 + rA) * APITCH + kk + cA));
#pragma unroll
            for (int np = 0; np < 2; np++)
                ldsm_x4(bv[np], Bs_u + 4u * ((wn + np * 16 + rB) * APITCH + kk + cB));
#pragma unroll
            for (int mt = 0; mt < 4; mt++)
#pragma unroll
                for (int np = 0; np < 2; np++) {
                    mma_tf32(acc[mt][2 * np],     av[mt], &bv[np][0]);
                    mma_tf32(acc[mt][2 * np + 1], av[mt], &bv[np][2]);
                }
        }
        __syncthreads();
    }

#pragma unroll
    for (int mt = 0; mt < 4; mt++) {
        const int r0 = bm + wm + mt * 16 + gid;
#pragma unroll
        for (int half = 0; half < 2; half++) {
            const int r = r0 + half * 8;
            const int b = r >> 11;
            const int s = r & (SEQ - 1);
#pragma unroll
            for (int nt = 0; nt < 4; nt++) {
                const int col = bn + wn + nt * 8 + tig * 2;
                float2 v = make_float2(acc[mt][nt][half * 2],
                                       acc[mt][nt][half * 2 + 1]);
                if (mode == 0) {
                    *(float2*)(C + (size_t)r * DMODEL + col) = v;
                } else {
                    const int h  = col >> 6;
                    const int kk = col & (DKEY - 1);
                    *(float2*)(C + ((((size_t)b * HEADS + h) * SEQ) + s) * DKEY + kk) = v;
                }
            }
        }
    }
}

// ======================= Flash attention (tf32 mma.sync + ldmatrix) ===========
// CTA: 128 queries, 4 warps (128 threads); warp w owns 32 q rows [w*32, w*32+32)
// as two m16 tiles. KV tiles of 64. Halved redundant K/V smem traffic vs 8-warp.
static constexpr int FQ = 128, FK = 64, FPP = 68;
static constexpr float SM_SCALE = 0.18033688011117310f; // (1/8) * log2(e)
static constexpr int FLASH_SMEM = (FQ * FPP * 2 + FK * FPP * 2) * 4;  // 104448 B

__global__ void __launch_bounds__(128, 2) flash_mma_kernel()
{
    extern __shared__ float sm[];
    float* Qs = sm;                    // [128 q][68]  (d in cols, tf32, pre-scaled)
    float* Ks = Qs + FQ * FPP;         // [64 kv][68]  (d in cols)  == B [n][k]
    float* Vt = Ks + FK * FPP;         // [64 d][68]   (kv in cols) == B [n][k]
    float* Ps = Vt + FK * FPP;         // [128 q][68]  (kv in cols)

    const int b  = blockIdx.z;
    const int h  = blockIdx.y;
    const int qt = blockIdx.x;
    const int tid  = threadIdx.x;
    const int w    = tid >> 5;    // 0..3
    const int lane = tid & 31;
    const int gid  = lane >> 2;   // 0..7
    const int tig  = lane & 3;    // 0..3
    const int qw   = w * 32;      // warp's q-row base inside tile

    // ldmatrix lane-address components (verified mapping)
    const int rA = lane & 15;
    const int cA = (lane >> 4) * 4;
    const int rB = (lane & 7) + ((lane >> 4) << 3);
    const int cB = ((lane >> 3) & 1) * 4;
    const uint32_t Qs_u = smem_u32(Qs);
    const uint32_t Ks_u = smem_u32(Ks);
    const uint32_t Vt_u = smem_u32(Vt);
    const uint32_t Ps_u = smem_u32(Ps);

    const float* Qg = g_qp + (((size_t)b * HEADS + h) * SEQ + (size_t)qt * FQ) * DKEY;
    const float* Kg = g_kp + ((size_t)b * HEADS + h) * SEQ * DKEY;
    const float* Vg = g_vp + ((size_t)b * HEADS + h) * SEQ * DKEY;

    // Load Q tile [128][64], scale by SM_SCALE, round to tf32.
#pragma unroll
    for (int it = 0; it < 16; it++) {
        int idx = tid + it * 128;      // 0..2047
        int row = idx >> 4;            // 0..127
        int dq  = idx & 15;            // 0..15
        float4 v = *(const float4*)(Qg + (size_t)row * DKEY + dq * 4);
        v.x = to_tf32(v.x * SM_SCALE);
        v.y = to_tf32(v.y * SM_SCALE);
        v.z = to_tf32(v.z * SM_SCALE);
        v.w = to_tf32(v.w * SM_SCALE);
        *(float4*)&Qs[row * FPP + dq * 4] = v;
    }

    float o[2][8][4];
    float mrun[2][2], lrun[2][2];
#pragma unroll
    for (int mt = 0; mt < 2; mt++) {
        mrun[mt][0] = -3.0e38f; mrun[mt][1] = -3.0e38f;
        lrun[mt][0] = 0.0f;     lrun[mt][1] = 0.0f;
#pragma unroll
        for (int nt = 0; nt < 8; nt++)
#pragma unroll
            for (int r = 0; r < 4; r++) o[mt][nt][r] = 0.0f;
    }

    for (int t = 0; t < SEQ / FK; t++) {
        const float* Kt = Kg + (size_t)t * FK * DKEY;
        const float* Vtg = Vg + (size_t)t * FK * DKEY;
        // K tile [64 kv][64 d] -> Ks[kv][d]  (vectorized)
#pragma unroll
        for (int it = 0; it < 8; it++) {
            int idx = tid + it * 128;
            int row = idx >> 4;        // kv 0..63
            int dq  = idx & 15;
            float4 kv = *(const float4*)(Kt + (size_t)row * DKEY + dq * 4);
            kv.x = to_tf32(kv.x); kv.y = to_tf32(kv.y);
            kv.z = to_tf32(kv.z); kv.w = to_tf32(kv.w);
            *(float4*)&Ks[row * FPP + dq * 4] = kv;
        }
        // V tile transposed -> Vt[d][kv]. STS banks = const+kv: conflict-free.
#pragma unroll
        for (int it = 0; it < 8; it++) {
            int idx = tid + it * 128;  // 0..1023
            int kv  = idx & 63;
            int dq  = idx >> 6;        // 0..15
            float4 vv = *(const float4*)(Vtg + (size_t)kv * DKEY + dq * 4);
            Vt[(dq * 4 + 0) * FPP + kv] = to_tf32(vv.x);
            Vt[(dq * 4 + 1) * FPP + kv] = to_tf32(vv.y);
            Vt[(dq * 4 + 2) * FPP + kv] = to_tf32(vv.z);
            Vt[(dq * 4 + 3) * FPP + kv] = to_tf32(vv.w);
        }
        __syncthreads();   // K,V ready; all prior-iter reads complete

        // S = Q * K^T : warp computes [32 q][64 kv]
        float s[2][8][4];
#pragma unroll
        for (int mt = 0; mt < 2; mt++)
#pragma unroll
            for (int nt = 0; nt < 8; nt++)
#pragma unroll
                for (int r = 0; r < 4; r++) s[mt][nt][r] = 0.0f;

#pragma unroll
        for (int ks = 0; ks < 8; ks++) {
            const int kk = ks * 8;
            uint32_t a[2][4];
            ldsm_x4(a[0], Qs_u + 4u * ((qw + rA) * FPP + kk + cA));
            ldsm_x4(a[1], Qs_u + 4u * ((qw + 16 + rA) * FPP + kk + cA));
#pragma unroll
            for (int g = 0; g < 4; g++) {
                uint32_t bv[4];
                ldsm_x4(bv, Ks_u + 4u * ((g * 16 + rB) * FPP + kk + cB));
#pragma unroll
                for (int mt = 0; mt < 2; mt++) {
                    mma_tf32(s[mt][2 * g],     a[mt], &bv[0]);
                    mma_tf32(s[mt][2 * g + 1], a[mt], &bv[2]);
                }
            }
        }

        // Online softmax per m16 tile (log2 domain).
#pragma unroll
        for (int mt = 0; mt < 2; mt++) {
            const int rowP0 = (qw + mt * 16 + gid) * FPP;
            const int rowP1 = rowP0 + 8 * FPP;
            float mx0 = -3.0e38f, mx1 = -3.0e38f;
#pragma unroll
            for (int nt = 0; nt < 8; nt++) {
                mx0 = fmaxf(mx0, fmaxf(s[mt][nt][0], s[mt][nt][1]));
                mx1 = fmaxf(mx1, fmaxf(s[mt][nt][2], s[mt][nt][3]));
            }
            mx0 = fmaxf(mx0, __shfl_xor_sync(0xffffffffu, mx0, 1));
            mx0 = fmaxf(mx0, __shfl_xor_sync(0xffffffffu, mx0, 2));
            mx1 = fmaxf(mx1, __shfl_xor_sync(0xffffffffu, mx1, 1));
            mx1 = fmaxf(mx1, __shfl_xor_sync(0xffffffffu, mx1, 2));

            float mn0 = fmaxf(mrun[mt][0], mx0);
            float mn1 = fmaxf(mrun[mt][1], mx1);
            float c0 = fast_exp2(mrun[mt][0] - mn0);
            float c1 = fast_exp2(mrun[mt][1] - mn1);
            mrun[mt][0] = mn0; mrun[mt][1] = mn1;

            float rs0 = 0.0f, rs1 = 0.0f;
#pragma unroll
            for (int nt = 0; nt < 8; nt++) {
                float p0 = fast_exp2(s[mt][nt][0] - mn0);
                float p1 = fast_exp2(s[mt][nt][1] - mn0);
                float p2 = fast_exp2(s[mt][nt][2] - mn1);
                float p3 = fast_exp2(s[mt][nt][3] - mn1);
                rs0 += p0 + p1;
                rs1 += p2 + p3;
                *(float2*)&Ps[rowP0 + nt * 8 + tig * 2] =
                    make_float2(to_tf32(p0), to_tf32(p1));
                *(float2*)&Ps[rowP1 + nt * 8 + tig * 2] =
                    make_float2(to_tf32(p2), to_tf32(p3));
                o[mt][nt][0] *= c0; o[mt][nt][1] *= c0;
                o[mt][nt][2] *= c1; o[mt][nt][3] *= c1;
            }
            rs0 += __shfl_xor_sync(0xffffffffu, rs0, 1);
            rs0 += __shfl_xor_sync(0xffffffffu, rs0, 2);
            rs1 += __shfl_xor_sync(0xffffffffu, rs1, 1);
            rs1 += __shfl_xor_sync(0xffffffffu, rs1, 2);
            lrun[mt][0] = lrun[mt][0] * c0 + rs0;
            lrun[mt][1] = lrun[mt][1] * c1 + rs1;
        }
        __syncwarp();   // this warp's P rows visible to this warp

        // O += P * V : A = Ps rows (ldmatrix), B = Vt rows (ldmatrix)
#pragma unroll
        for (int ks = 0; ks < 8; ks++) {
            const int kk = ks * 8;
            uint32_t a[2][4];
            ldsm_x4(a[0], Ps_u + 4u * ((qw + rA) * FPP + kk + cA));
            ldsm_x4(a[1], Ps_u + 4u * ((qw + 16 + rA) * FPP + kk + cA));
#pragma unroll
            for (int g = 0; g < 4; g++) {
                uint32_t bv[4];
                ldsm_x4(bv, Vt_u + 4u * ((g * 16 + rB) * FPP + kk + cB));
#pragma unroll
                for (int mt = 0; mt < 2; mt++) {
                    mma_tf32(o[mt][2 * g],     a[mt], &bv[0]);
                    mma_tf32(o[mt][2 * g + 1], a[mt], &bv[2]);
                }
            }
        }
        __syncthreads();   // all K/V/P reads done before next iteration's loads
    }

    // Epilogue: normalize, write concat-head layout [B*S, H*K]
#pragma unroll
    for (int mt = 0; mt < 2; mt++) {
        const float inv0 = 1.0f / lrun[mt][0];
        const float inv1 = 1.0f / lrun[mt][1];
        const size_t m0 = (size_t)b * SEQ + (size_t)qt * FQ + qw + mt * 16 + gid;
        const size_t m1 = m0 + 8;
#pragma unroll
        for (int nt = 0; nt < 8; nt++) {
            const int col = h * DKEY + nt * 8 + tig * 2;
            *(float2*)(g_ao + m0 * DMODEL + col) =
                make_float2(o[mt][nt][0] * inv0, o[mt][nt][1] * inv0);
            *(float2*)(g_ao + m1 * DMODEL + col) =
                make_float2(o[mt][nt][2] * inv1, o[mt][nt][3] * inv1);
        }
    }
}

// ======================= launch =======================
extern "C" void kernel_launch(void* const* d_in, const int* in_sizes, int n_in,
                              void* d_out, int out_size)
{
    const float* q_in  = (const float*)d_in[0];
    const float* k_in  = (const float*)d_in[1];
    const float* v_in  = (const float*)d_in[2];
    const float* Wq    = (const float*)d_in[3];
    const float* Wk    = (const float*)d_in[4];
    const float* Wv    = (const float*)d_in[5];
    const float* Wo    = (const float*)d_in[6];
    float* out = (float*)d_out;

    float *qp, *kp, *vp, *ao;
    cudaGetSymbolAddress((void**)&qp, g_qp);
    cudaGetSymbolAddress((void**)&kp, g_kp);
    cudaGetSymbolAddress((void**)&vp, g_vp);
    cudaGetSymbolAddress((void**)&ao, g_ao);

    dim3 ggrid(DMODEL / BN, MROWS / BM);   // (8, 64)

    gemm_mma_kernel<<<ggrid, 256>>>(q_in, Wq, qp, 1);
    gemm_mma_kernel<<<ggrid, 256>>>(k_in, Wk, kp, 1);
    gemm_mma_kernel<<<ggrid, 256>>>(v_in, Wv, vp, 1);

    cudaFuncSetAttribute(flash_mma_kernel,
                         cudaFuncAttributeMaxDynamicSharedMemorySize,
                         FLASH_SMEM);
    flash_mma_kernel<<<dim3(SEQ / FQ, HEADS, BATCH), 128, FLASH_SMEM>>>();

    gemm_mma_kernel<<<ggrid, 256>>>(ao, Wo, out, 0);
}

// round 14
// speedup vs baseline: 3.5048x; 1.0088x over previous
#include <cuda_runtime.h>
#include <cstdint>
#include <cstddef>

// Problem constants
#define DMODEL 1024
#define HEADS  16
#define DKEY   64
#define BATCH  4
#define SEQ    2048
#define MROWS  (BATCH * SEQ)   // 8192

// -------- scratch (static device arrays; no allocation allowed) --------
__device__ float g_qp[(size_t)BATCH * HEADS * SEQ * DKEY];  // [B,H,S,K] tf32, pre-scaled
__device__ float g_kp[(size_t)BATCH * HEADS * SEQ * DKEY];  // [B,H,S,K] tf32
__device__ float g_vt[(size_t)BATCH * HEADS * DKEY * SEQ];  // [B,H,K,S] tf32 (V transposed)
__device__ float g_ao[(size_t)MROWS * DMODEL];              // [B*S, H*K] fp32

static constexpr float SM_SCALE = 0.18033688011117310f; // (1/8) * log2(e)

__device__ __forceinline__ float fast_exp2(float x) {
    float y;
    asm("ex2.approx.f32 %0, %1;" : "=f"(y) : "f"(x));
    return y;
}
__device__ __forceinline__ float to_tf32(float x) {
    float y;
    asm("cvt.rna.tf32.f32 %0, %1;" : "=f"(y) : "f"(x));
    return y;
}
__device__ __forceinline__ uint32_t smem_u32(const void* p) {
    uint32_t a;
    asm("{ .reg .u64 t; cvta.to.shared.u64 t, %1; cvt.u32.u64 %0, t; }" : "=r"(a) : "l"(p));
    return a;
}

// m16n8k8 tf32 mma: D = A(16x8,row) * B(8x8,col) + D
__device__ __forceinline__ void mma_tf32(float* c, const uint32_t* a, const uint32_t* b) {
    asm volatile(
        "mma.sync.aligned.m16n8k8.row.col.f32.tf32.tf32.f32 "
        "{%0,%1,%2,%3}, {%4,%5,%6,%7}, {%8,%9}, {%0,%1,%2,%3};"
        : "+f"(c[0]), "+f"(c[1]), "+f"(c[2]), "+f"(c[3])
        : "r"(a[0]), "r"(a[1]), "r"(a[2]), "r"(a[3]), "r"(b[0]), "r"(b[1]));
}

// ldmatrix x4 (bit-mover; fp32/tf32 data, 8x4-f32 tiles seen as 8x8-b16)
__device__ __forceinline__ void ldsm_x4(uint32_t* r, uint32_t addr) {
    asm volatile("ldmatrix.sync.aligned.m8n8.x4.shared.b16 {%0,%1,%2,%3}, [%4];"
                 : "=r"(r[0]), "=r"(r[1]), "=r"(r[2]), "=r"(r[3]) : "r"(addr));
}

// cp.async 16B
__device__ __forceinline__ void cp_async16(uint32_t dst, const void* src) {
    asm volatile("cp.async.cg.shared.global [%0], [%1], 16;" :: "r"(dst), "l"(src));
}
#define CP_COMMIT() asm volatile("cp.async.commit_group;" ::: "memory")
#define CP_WAIT(n)  asm volatile("cp.async.wait_group %0;" :: "n"(n) : "memory")

// ============ tf32 GEMM mainloop (fills acc), tiles 128x128, BK=32 ============
static constexpr int BM = 128, BN = 128, BK = 32;
static constexpr int APITCH = 36;

__device__ __forceinline__ void gemm_mainloop(
    const float* __restrict__ A, const float* __restrict__ B,
    float* As, float* Bs, int bm, int bn, float acc[4][4][4])
{
    const int tid  = threadIdx.x;
    const int wid  = tid >> 5;
    const int lane = tid & 31;
    const int wm = (wid >> 2) * 64;
    const int wn = (wid & 3) * 32;

    const int rA = lane & 15;
    const int cA = (lane >> 4) * 4;
    const int rB = (lane & 7) + ((lane >> 4) << 3);
    const int cB = ((lane >> 3) & 1) * 4;
    const uint32_t As_u = smem_u32(As);
    const uint32_t Bs_u = smem_u32(Bs);

    const int ldrow = tid >> 3;
    const int ldkq  = tid & 7;

#pragma unroll
    for (int mt = 0; mt < 4; mt++)
#pragma unroll
        for (int nt = 0; nt < 4; nt++)
#pragma unroll
            for (int r = 0; r < 4; r++) acc[mt][nt][r] = 0.0f;

    float4 pa[4], pb[4];
#pragma unroll
    for (int it = 0; it < 4; it++) {
        int row = ldrow + it * 32;
        pa[it] = *(const float4*)(A + (size_t)(bm + row) * DMODEL + ldkq * 4);
        pb[it] = *(const float4*)(B + (size_t)(bn + row) * DMODEL + ldkq * 4);
    }

    for (int k0 = 0; k0 < DMODEL; k0 += BK) {
#pragma unroll
        for (int it = 0; it < 4; it++) {
            int row = ldrow + it * 32;
            float4 va = pa[it];
            va.x = to_tf32(va.x); va.y = to_tf32(va.y);
            va.z = to_tf32(va.z); va.w = to_tf32(va.w);
            *(float4*)&As[row * APITCH + ldkq * 4] = va;
            float4 vb = pb[it];
            vb.x = to_tf32(vb.x); vb.y = to_tf32(vb.y);
            vb.z = to_tf32(vb.z); vb.w = to_tf32(vb.w);
            *(float4*)&Bs[row * APITCH + ldkq * 4] = vb;
        }
        __syncthreads();

        if (k0 + BK < DMODEL) {
#pragma unroll
            for (int it = 0; it < 4; it++) {
                int row = ldrow + it * 32;
                pa[it] = *(const float4*)(A + (size_t)(bm + row) * DMODEL + k0 + BK + ldkq * 4);
                pb[it] = *(const float4*)(B + (size_t)(bn + row) * DMODEL + k0 + BK + ldkq * 4);
            }
        }

#pragma unroll
        for (int ks = 0; ks < 4; ks++) {
            const int kk = ks * 8;
            uint32_t av[4][4], bv[2][4];
#pragma unroll
            for (int mt = 0; mt < 4; mt++)
                ldsm_x4(av[mt], As_u + 4u * ((wm + mt * 16 + rA) * APITCH + kk + cA));
#pragma unroll
            for (int np = 0; np < 2; np++)
                ldsm_x4(bv[np], Bs_u + 4u * ((wn + np * 16 + rB) * APITCH + kk + cB));
#pragma unroll
            for (int mt = 0; mt < 4; mt++)
#pragma unroll
                for (int np = 0; np < 2; np++) {
                    mma_tf32(acc[mt][2 * np],     av[mt], &bv[np][0]);
                    mma_tf32(acc[mt][2 * np + 1], av[mt], &bv[np][2]);
                }
        }
        __syncthreads();
    }
}

// Fused QKV projection GEMMs. z=0: Q (scale+rna, scatter [B,H,S,K]);
// z=1: K (rna, scatter); z=2: V (rna, transposed scatter [B,H,K,S]).
__global__ void __launch_bounds__(256) qkv_gemm_kernel(
    const float* __restrict__ q_in, const float* __restrict__ k_in,
    const float* __restrict__ v_in,
    const float* __restrict__ Wq, const float* __restrict__ Wk,
    const float* __restrict__ Wv,
    float* __restrict__ qp, float* __restrict__ kp, float* __restrict__ vt)
{
    __shared__ float As[BM * APITCH];
    __shared__ float Bs[BN * APITCH];

    const int z = blockIdx.z;
    const float* A = (z == 0) ? q_in : (z == 1) ? k_in : v_in;
    const float* B = (z == 0) ? Wq : (z == 1) ? Wk : Wv;
    const int bm = blockIdx.y * BM;
    const int bn = blockIdx.x * BN;

    float acc[4][4][4];
    gemm_mainloop(A, B, As, Bs, bm, bn, acc);

    const int tid  = threadIdx.x;
    const int wid  = tid >> 5;
    const int lane = tid & 31;
    const int gid  = lane >> 2;
    const int tig  = lane & 3;
    const int wm = (wid >> 2) * 64;
    const int wn = (wid & 3) * 32;
    const float sc = (z == 0) ? SM_SCALE : 1.0f;

#pragma unroll
    for (int mt = 0; mt < 4; mt++) {
        const int r0 = bm + wm + mt * 16 + gid;
#pragma unroll
        for (int half = 0; half < 2; half++) {
            const int r = r0 + half * 8;
            const int b = r >> 11;
            const int s = r & (SEQ - 1);
#pragma unroll
            for (int nt = 0; nt < 4; nt++) {
                const int col = bn + wn + nt * 8 + tig * 2;
                const int h  = col >> 6;
                const int kk = col & (DKEY - 1);
                float c0 = to_tf32(acc[mt][nt][half * 2] * sc);
                float c1 = to_tf32(acc[mt][nt][half * 2 + 1] * sc);
                if (z == 2) {
                    float* p = vt + (((size_t)b * HEADS + h) * DKEY + kk) * SEQ + s;
                    p[0]   = c0;
                    p[SEQ] = c1;   // kk+1
                } else {
                    float* dst = (z == 0) ? qp : kp;
                    *(float2*)(dst + ((((size_t)b * HEADS + h) * SEQ) + s) * DKEY + kk) =
                        make_float2(c0, c1);
                }
            }
        }
    }
}

// Output projection GEMM: C = A * Wo^T, plain row-major out.
__global__ void __launch_bounds__(256) out_gemm_kernel(
    const float* __restrict__ A, const float* __restrict__ B,
    float* __restrict__ C)
{
    __shared__ float As[BM * APITCH];
    __shared__ float Bs[BN * APITCH];

    const int bm = blockIdx.y * BM;
    const int bn = blockIdx.x * BN;
    float acc[4][4][4];
    gemm_mainloop(A, B, As, Bs, bm, bn, acc);

    const int tid  = threadIdx.x;
    const int wid  = tid >> 5;
    const int lane = tid & 31;
    const int gid  = lane >> 2;
    const int tig  = lane & 3;
    const int wm = (wid >> 2) * 64;
    const int wn = (wid & 3) * 32;

#pragma unroll
    for (int mt = 0; mt < 4; mt++) {
        const int r0 = bm + wm + mt * 16 + gid;
#pragma unroll
        for (int half = 0; half < 2; half++) {
            const int r = r0 + half * 8;
#pragma unroll
            for (int nt = 0; nt < 4; nt++) {
                const int col = bn + wn + nt * 8 + tig * 2;
                *(float2*)(C + (size_t)r * DMODEL + col) =
                    make_float2(acc[mt][nt][half * 2], acc[mt][nt][half * 2 + 1]);
            }
        }
    }
}

// ============== Flash attention (tf32 mma + ldmatrix + cp.async) ==============
// CTA: 256 queries, 8 warps x 32 q rows. KV tiles of 64, double-buffered via
// cp.async. All operands pre-converted (tf32 / pre-scaled / V pre-transposed).
static constexpr int FQ = 256, FK = 64, FPP = 68;
// smem: Qs(256*68) + Ps(256*68) + 2*K(64*68) + 2*V(64*68) floats
static constexpr int SM_QS = 0;
static constexpr int SM_PS = FQ * FPP;
static constexpr int SM_K0 = SM_PS + FQ * FPP;
static constexpr int SM_V0 = SM_K0 + FK * FPP;
static constexpr int SM_K1 = SM_V0 + FK * FPP;
static constexpr int SM_V1 = SM_K1 + FK * FPP;
static constexpr int FLASH_SMEM = (SM_V1 + FK * FPP) * 4;   // 208896 B

__global__ void __launch_bounds__(256, 1) flash_mma_kernel()
{
    extern __shared__ float sm[];
    const uint32_t sm_u = smem_u32(sm);
    const uint32_t Qs_u = sm_u + 4u * SM_QS;
    const uint32_t Ps_u = sm_u + 4u * SM_PS;
    const uint32_t Kb_u[2] = { sm_u + 4u * SM_K0, sm_u + 4u * SM_K1 };
    const uint32_t Vb_u[2] = { sm_u + 4u * SM_V0, sm_u + 4u * SM_V1 };
    float* Ps = sm + SM_PS;

    const int b  = blockIdx.z;
    const int h  = blockIdx.y;
    const int qt = blockIdx.x;
    const int tid  = threadIdx.x;
    const int w    = tid >> 5;    // 0..7
    const int lane = tid & 31;
    const int gid  = lane >> 2;
    const int tig  = lane & 3;
    const int qw   = w * 32;      // warp's q-row base

    const int rA = lane & 15;
    const int cA = (lane >> 4) * 4;
    const int rB = (lane & 7) + ((lane >> 4) << 3);
    const int cB = ((lane >> 3) & 1) * 4;

    const float* Qg = g_qp + (((size_t)b * HEADS + h) * SEQ + (size_t)qt * FQ) * DKEY;
    const float* Kg = g_kp + ((size_t)b * HEADS + h) * SEQ * DKEY;
    const float* Vg = g_vt + ((size_t)b * HEADS + h) * DKEY * SEQ;

    // Q: 4096 chunks (256 rows x 16)
#pragma unroll
    for (int it = 0; it < 16; it++) {
        int idx = tid + it * 256;
        int row = idx >> 4;
        int cq  = idx & 15;
        cp_async16(Qs_u + 4u * (row * FPP) + cq * 16u, Qg + (size_t)row * DKEY + cq * 4);
    }
    // K0 / V0: 1024 chunks each (64 rows x 16)
    {
        int row = tid >> 2;        // 0..63
        int cq4 = (tid & 3) * 4;   // chunk group: 4 consecutive chunks per thread
#pragma unroll
        for (int c = 0; c < 4; c++) {
            cp_async16(Kb_u[0] + 4u * (row * FPP) + (cq4 + c) * 16u,
                       Kg + (size_t)row * DKEY + (cq4 + c) * 4);
            cp_async16(Vb_u[0] + 4u * (row * FPP) + (cq4 + c) * 16u,
                       Vg + (size_t)row * SEQ + (cq4 + c) * 4);
        }
    }
    CP_COMMIT();

    float o[2][8][4];
    float mrun[2][2], lrun[2][2];
#pragma unroll
    for (int mt = 0; mt < 2; mt++) {
        mrun[mt][0] = -3.0e38f; mrun[mt][1] = -3.0e38f;
        lrun[mt][0] = 0.0f;     lrun[mt][1] = 0.0f;
#pragma unroll
        for (int nt = 0; nt < 8; nt++)
#pragma unroll
            for (int r = 0; r < 4; r++) o[mt][nt][r] = 0.0f;
    }

    const int NT = SEQ / FK;   // 32
    for (int t = 0; t < NT; t++) {
        const int p = t & 1;
        // Prefetch tile t+1 into the other buffer (its prior reads finished
        // at the end-of-iter barrier of t-1).
        if (t + 1 < NT) {
            const int np = 1 - p;
            const float* Kt = Kg + (size_t)(t + 1) * FK * DKEY;
            const float* Vt = Vg + (size_t)(t + 1) * FK;
            int row = tid >> 2;
            int cq4 = (tid & 3) * 4;
#pragma unroll
            for (int c = 0; c < 4; c++) {
                cp_async16(Kb_u[np] + 4u * (row * FPP) + (cq4 + c) * 16u,
                           Kt + (size_t)row * DKEY + (cq4 + c) * 4);
                cp_async16(Vb_u[np] + 4u * (row * FPP) + (cq4 + c) * 16u,
                           Vt + (size_t)row * SEQ + (cq4 + c) * 4);
            }
            CP_COMMIT();
            CP_WAIT(1);   // tile t (and Q on t=0) complete; t+1 may be pending
        } else {
            CP_WAIT(0);
        }
        __syncthreads();   // cp.async data visible to all warps

        const uint32_t Ks_u = Kb_u[p];
        const uint32_t Vt_u = Vb_u[p];

        // S = Q * K^T : warp computes [32 q][64 kv]
        float s[2][8][4];
#pragma unroll
        for (int mt = 0; mt < 2; mt++)
#pragma unroll
            for (int nt = 0; nt < 8; nt++)
#pragma unroll
                for (int r = 0; r < 4; r++) s[mt][nt][r] = 0.0f;

#pragma unroll
        for (int ks = 0; ks < 8; ks++) {
            const int kk = ks * 8;
            uint32_t a[2][4];
            ldsm_x4(a[0], Qs_u + 4u * ((qw + rA) * FPP + kk + cA));
            ldsm_x4(a[1], Qs_u + 4u * ((qw + 16 + rA) * FPP + kk + cA));
#pragma unroll
            for (int g = 0; g < 4; g++) {
                uint32_t bv[4];
                ldsm_x4(bv, Ks_u + 4u * ((g * 16 + rB) * FPP + kk + cB));
#pragma unroll
                for (int mt = 0; mt < 2; mt++) {
                    mma_tf32(s[mt][2 * g],     a[mt], &bv[0]);
                    mma_tf32(s[mt][2 * g + 1], a[mt], &bv[2]);
                }
            }
        }

        // Online softmax per m16 tile (log2 domain; Q pre-scaled).
#pragma unroll
        for (int mt = 0; mt < 2; mt++) {
            const int rowP0 = (qw + mt * 16 + gid) * FPP;
            const int rowP1 = rowP0 + 8 * FPP;
            float mx0 = -3.0e38f, mx1 = -3.0e38f;
#pragma unroll
            for (int nt = 0; nt < 8; nt++) {
                mx0 = fmaxf(mx0, fmaxf(s[mt][nt][0], s[mt][nt][1]));
                mx1 = fmaxf(mx1, fmaxf(s[mt][nt][2], s[mt][nt][3]));
            }
            mx0 = fmaxf(mx0, __shfl_xor_sync(0xffffffffu, mx0, 1));
            mx0 = fmaxf(mx0, __shfl_xor_sync(0xffffffffu, mx0, 2));
            mx1 = fmaxf(mx1, __shfl_xor_sync(0xffffffffu, mx1, 1));
            mx1 = fmaxf(mx1, __shfl_xor_sync(0xffffffffu, mx1, 2));

            float mn0 = fmaxf(mrun[mt][0], mx0);
            float mn1 = fmaxf(mrun[mt][1], mx1);
            float c0 = fast_exp2(mrun[mt][0] - mn0);
            float c1 = fast_exp2(mrun[mt][1] - mn1);
            mrun[mt][0] = mn0; mrun[mt][1] = mn1;

            float rs0 = 0.0f, rs1 = 0.0f;
#pragma unroll
            for (int nt = 0; nt < 8; nt++) {
                float p0 = fast_exp2(s[mt][nt][0] - mn0);
                float p1 = fast_exp2(s[mt][nt][1] - mn0);
                float p2 = fast_exp2(s[mt][nt][2] - mn1);
                float p3 = fast_exp2(s[mt][nt][3] - mn1);
                rs0 += p0 + p1;
                rs1 += p2 + p3;
                *(float2*)&Ps[rowP0 + nt * 8 + tig * 2] =
                    make_float2(to_tf32(p0), to_tf32(p1));
                *(float2*)&Ps[rowP1 + nt * 8 + tig * 2] =
                    make_float2(to_tf32(p2), to_tf32(p3));
                o[mt][nt][0] *= c0; o[mt][nt][1] *= c0;
                o[mt][nt][2] *= c1; o[mt][nt][3] *= c1;
            }
            rs0 += __shfl_xor_sync(0xffffffffu, rs0, 1);
            rs0 += __shfl_xor_sync(0xffffffffu, rs0, 2);
            rs1 += __shfl_xor_sync(0xffffffffu, rs1, 1);
            rs1 += __shfl_xor_sync(0xffffffffu, rs1, 2);
            lrun[mt][0] = lrun[mt][0] * c0 + rs0;
            lrun[mt][1] = lrun[mt][1] * c1 + rs1;
        }
        __syncwarp();   // this warp's P rows visible to this warp

        // O += P * V
#pragma unroll
        for (int ks = 0; ks < 8; ks++) {
            const int kk = ks * 8;
            uint32_t a[2][4];
            ldsm_x4(a[0], Ps_u + 4u * ((qw + rA) * FPP + kk + cA));
            ldsm_x4(a[1], Ps_u + 4u * ((qw + 16 + rA) * FPP + kk + cA));
#pragma unroll
            for (int g = 0; g < 4; g++) {
                uint32_t bv[4];
                ldsm_x4(bv, Vt_u + 4u * ((g * 16 + rB) * FPP + kk + cB));
#pragma unroll
                for (int mt = 0; mt < 2; mt++) {
                    mma_tf32(o[mt][2 * g],     a[mt], &bv[0]);
                    mma_tf32(o[mt][2 * g + 1], a[mt], &bv[2]);
                }
            }
        }
        __syncthreads();   // buffer reads done before next iter's cp.async issue
    }

    // Epilogue: normalize, write concat-head layout [B*S, H*K]
#pragma unroll
    for (int mt = 0; mt < 2; mt++) {
        const float inv0 = 1.0f / lrun[mt][0];
        const float inv1 = 1.0f / lrun[mt][1];
        const size_t m0 = (size_t)b * SEQ + (size_t)qt * FQ + qw + mt * 16 + gid;
        const size_t m1 = m0 + 8;
#pragma unroll
        for (int nt = 0; nt < 8; nt++) {
            const int col = h * DKEY + nt * 8 + tig * 2;
            *(float2*)(g_ao + m0 * DMODEL + col) =
                make_float2(o[mt][nt][0] * inv0, o[mt][nt][1] * inv0);
            *(float2*)(g_ao + m1 * DMODEL + col) =
                make_float2(o[mt][nt][2] * inv1, o[mt][nt][3] * inv1);
        }
    }
}

// ======================= launch =======================
extern "C" void kernel_launch(void* const* d_in, const int* in_sizes, int n_in,
                              void* d_out, int out_size)
{
    const float* q_in  = (const float*)d_in[0];
    const float* k_in  = (const float*)d_in[1];
    const float* v_in  = (const float*)d_in[2];
    const float* Wq    = (const float*)d_in[3];
    const float* Wk    = (const float*)d_in[4];
    const float* Wv    = (const float*)d_in[5];
    const float* Wo    = (const float*)d_in[6];
    float* out = (float*)d_out;

    float *qp, *kp, *vt, *ao;
    cudaGetSymbolAddress((void**)&qp, g_qp);
    cudaGetSymbolAddress((void**)&kp, g_kp);
    cudaGetSymbolAddress((void**)&vt, g_vt);
    cudaGetSymbolAddress((void**)&ao, g_ao);

    // Fused Q/K/V projections: grid.z selects which projection
    qkv_gemm_kernel<<<dim3(DMODEL / BN, MROWS / BM, 3), 256>>>(
        q_in, k_in, v_in, Wq, Wk, Wv, qp, kp, vt);

    cudaFuncSetAttribute(flash_mma_kernel,
                         cudaFuncAttributeMaxDynamicSharedMemorySize,
                         FLASH_SMEM);
    flash_mma_kernel<<<dim3(SEQ / FQ, HEADS, BATCH), 256, FLASH_SMEM>>>();

    out_gemm_kernel<<<dim3(DMODEL / BN, MROWS / BM), 256>>>(ao, Wo, out);
}